// round 6
// baseline (speedup 1.0000x reference)
#include <cuda_runtime.h>
#include <cuda_fp16.h>
#include <cstdint>
#include <math.h>

#define N_NODES  50000
#define N_HEDGES 50000
#define NNZ      800000
#define F_IN     256
#define HID      256
#define F_OUT    128

// ---------------- scratch (device globals; no allocs allowed) ----------------
__device__ __align__(128) float g_bufA[N_NODES * HID];  // msg (fp16, reinterpreted)
__device__ __align__(128) float g_bufB[N_NODES * HID];  // xe  (fp16, reinterpreted)
__device__ __align__(128) float g_bufC[N_NODES * HID];  // h   (fp32)
__device__ __align__(128) float g_inv_v[N_NODES];
__device__ __align__(128) float g_inv_e[N_HEDGES];
__device__ __align__(128) int   g_cnt_v[N_NODES];
__device__ __align__(128) int   g_cnt_e[N_HEDGES];
__device__ __align__(128) int   g_cur_v[N_NODES];
__device__ __align__(128) int   g_cur_e[N_HEDGES];
__device__ __align__(128) int   g_off_v[N_NODES + 1];
__device__ __align__(128) int   g_off_e[N_HEDGES + 1];
__device__ __align__(128) int   g_vi[NNZ];
__device__ __align__(128) int   g_hi[NNZ];
__device__ __align__(128) int   g_nbr_e[NNZ];
__device__ __align__(128) int   g_nbr_v[NNZ];
__device__ int g_flag[1];

// ---------------- small utility kernels ----------------
__global__ void k_zero_i(int* p, int n) {
    int i = blockIdx.x * blockDim.x + threadIdx.x;
    if (i < n) p[i] = 0;
}

__global__ void k_detect(const int* __restrict__ ei) {
    if (blockIdx.x == 0 && threadIdx.x == 0) {
        int z = 0;
        #pragma unroll
        for (int i = 1; i < 64; i += 2) z |= ei[i];
        g_flag[0] = (z == 0) ? 1 : 0;
    }
}

__global__ void k_convert(const void* __restrict__ ei_raw) {
    int i = blockIdx.x * blockDim.x + threadIdx.x;
    if (i >= NNZ) return;
    int v, h;
    if (g_flag[0]) {
        const long long* e = (const long long*)ei_raw;
        v = (int)e[i];
        h = (int)e[NNZ + i];
    } else {
        const int* e = (const int*)ei_raw;
        v = e[i];
        h = e[NNZ + i];
    }
    g_vi[i] = v;
    g_hi[i] = h;
    atomicAdd(&g_cnt_v[v], 1);
    atomicAdd(&g_cnt_e[h], 1);
}

__global__ void k_invdeg() {
    int i = blockIdx.x * blockDim.x + threadIdx.x;
    if (i < N_NODES)  g_inv_v[i] = 1.0f / (float)max(g_cnt_v[i], 1);
    if (i < N_HEDGES) g_inv_e[i] = 1.0f / (float)max(g_cnt_e[i], 1);
}

__global__ void k_scan() {
    const int n = 50000;
    const int* cnt = blockIdx.x ? g_cnt_v : g_cnt_e;
    int* off       = blockIdx.x ? g_off_v : g_off_e;
    __shared__ int partial[1024];
    int t = threadIdx.x;
    const int PER = (n + 1023) / 1024;
    int base = t * PER;
    int s = 0;
    for (int i = 0; i < PER; i++) {
        int idx = base + i;
        if (idx < n) s += cnt[idx];
    }
    partial[t] = s;
    __syncthreads();
    for (int d = 1; d < 1024; d <<= 1) {
        int v = (t >= d) ? partial[t - d] : 0;
        __syncthreads();
        partial[t] += v;
        __syncthreads();
    }
    int run = (t == 0) ? 0 : partial[t - 1];
    for (int i = 0; i < PER; i++) {
        int idx = base + i;
        if (idx < n) { off[idx] = run; run += cnt[idx]; }
    }
    if (t == 1023) off[n] = run;
}

__global__ void k_fill() {
    int i = blockIdx.x * blockDim.x + threadIdx.x;
    if (i >= NNZ) return;
    int v = g_vi[i], h = g_hi[i];
    int pe = g_off_e[h] + atomicAdd(&g_cur_e[h], 1);
    g_nbr_e[pe] = v;
    int pv = g_off_v[v] + atomicAdd(&g_cur_v[v], 1);
    g_nbr_v[pv] = h;
}

// ---------------- TF32 tensor-core GEMM, fp16 output ----------------
__device__ __forceinline__ uint32_t f2tf32(float x) {
    uint32_t r;
    asm("cvt.rna.tf32.f32 %0, %1;" : "=r"(r) : "f"(x));
    return r;
}

__global__ __launch_bounds__(256, 2)
void k_tgemm(const float* __restrict__ A, const float* __restrict__ B,
             __half* __restrict__ C, int M, int K, int N) {
    __shared__ uint32_t As[2][8][132];
    __shared__ uint32_t Bs[2][8][132];
    const int t = threadIdx.x;
    const int lane = t & 31;
    const int warp = t >> 5;
    const int warp_m = (warp & 1) * 64;
    const int warp_n = (warp >> 1) * 32;
    const int gid = lane >> 2;
    const int tg  = lane & 3;

    const int arow = t >> 1, acol = (t & 1) * 4;
    const int brow = t >> 5, bcol = (t & 31) * 4;
    const int bm = blockIdx.y * 128, bn = blockIdx.x * 128;
    const bool arow_ok = (bm + arow) < M;
    const float* Ap = A + (size_t)(bm + arow) * K + acol;
    const float* Bp = B + (size_t)brow * N + bn + bcol;

    float acc[4][4][4] = {};
    float4 aReg, bReg;

    aReg = arow_ok ? *(const float4*)Ap : make_float4(0.f, 0.f, 0.f, 0.f);
    bReg = *(const float4*)Bp;
    As[0][acol + 0][arow] = f2tf32(aReg.x);
    As[0][acol + 1][arow] = f2tf32(aReg.y);
    As[0][acol + 2][arow] = f2tf32(aReg.z);
    As[0][acol + 3][arow] = f2tf32(aReg.w);
    Bs[0][brow][bcol + 0] = f2tf32(bReg.x);
    Bs[0][brow][bcol + 1] = f2tf32(bReg.y);
    Bs[0][brow][bcol + 2] = f2tf32(bReg.z);
    Bs[0][brow][bcol + 3] = f2tf32(bReg.w);
    __syncthreads();

    const int nk = K >> 3;
    for (int kt = 0; kt < nk; kt++) {
        const int cur = kt & 1, nxt = cur ^ 1;
        if (kt + 1 < nk) {
            aReg = arow_ok ? *(const float4*)(Ap + (kt + 1) * 8)
                           : make_float4(0.f, 0.f, 0.f, 0.f);
            bReg = *(const float4*)(Bp + (size_t)(kt + 1) * 8 * N);
        }

        uint32_t af[4][4], bf[4][2];
        #pragma unroll
        for (int mt = 0; mt < 4; mt++) {
            int r = warp_m + mt * 16 + gid;
            af[mt][0] = As[cur][tg][r];
            af[mt][1] = As[cur][tg][r + 8];
            af[mt][2] = As[cur][tg + 4][r];
            af[mt][3] = As[cur][tg + 4][r + 8];
        }
        #pragma unroll
        for (int nt = 0; nt < 4; nt++) {
            int c = warp_n + nt * 8 + gid;
            bf[nt][0] = Bs[cur][tg][c];
            bf[nt][1] = Bs[cur][tg + 4][c];
        }
        #pragma unroll
        for (int mt = 0; mt < 4; mt++)
            #pragma unroll
            for (int nt = 0; nt < 4; nt++) {
                asm volatile(
                    "mma.sync.aligned.m16n8k8.row.col.f32.tf32.tf32.f32 "
                    "{%0,%1,%2,%3}, {%4,%5,%6,%7}, {%8,%9}, {%0,%1,%2,%3};"
                    : "+f"(acc[mt][nt][0]), "+f"(acc[mt][nt][1]),
                      "+f"(acc[mt][nt][2]), "+f"(acc[mt][nt][3])
                    : "r"(af[mt][0]), "r"(af[mt][1]), "r"(af[mt][2]), "r"(af[mt][3]),
                      "r"(bf[nt][0]), "r"(bf[nt][1]));
            }

        if (kt + 1 < nk) {
            As[nxt][acol + 0][arow] = f2tf32(aReg.x);
            As[nxt][acol + 1][arow] = f2tf32(aReg.y);
            As[nxt][acol + 2][arow] = f2tf32(aReg.z);
            As[nxt][acol + 3][arow] = f2tf32(aReg.w);
            Bs[nxt][brow][bcol + 0] = f2tf32(bReg.x);
            Bs[nxt][brow][bcol + 1] = f2tf32(bReg.y);
            Bs[nxt][brow][bcol + 2] = f2tf32(bReg.z);
            Bs[nxt][brow][bcol + 3] = f2tf32(bReg.w);
        }
        __syncthreads();
    }

    #pragma unroll
    for (int mt = 0; mt < 4; mt++) {
        int r0 = bm + warp_m + mt * 16 + gid;
        #pragma unroll
        for (int nt = 0; nt < 4; nt++) {
            int c0 = bn + warp_n + nt * 8 + tg * 2;
            if (r0 < M)
                *(__half2*)&C[(size_t)r0 * N + c0] =
                    __floats2half2_rn(acc[mt][nt][0], acc[mt][nt][1]);
            if (r0 + 8 < M)
                *(__half2*)&C[(size_t)(r0 + 8) * N + c0] =
                    __floats2half2_rn(acc[mt][nt][2], acc[mt][nt][3]);
        }
    }
}

// ---------------- CSR gathers over fp16 rows (fp32 accumulate, MLP-4) --------
// LPG lanes per row; each lane owns 8 halves (one uint4). Unroll 4 neighbors:
// all 4 index loads + all 4 row loads issued before accumulation.
template<int LPG, int RPB, int HF_OUT>
__global__ __launch_bounds__(LPG * RPB)
void k_gather(const uint4* __restrict__ src,
              const int* __restrict__ off,
              const int* __restrict__ nbr,
              const float* __restrict__ dscale,
              const float* __restrict__ bias,
              void* __restrict__ dst, int nrows, int do_elu) {
    const int group = threadIdx.x / LPG;
    const int lane  = threadIdx.x % LPG;
    const int row = blockIdx.x * RPB + group;
    if (row >= nrows) return;
    const int s0 = off[row], s1 = off[row + 1];

    float2 acc0[4] = {};
    float2 acc1[4] = {};
    int j = s0;
    for (; j + 3 < s1; j += 4) {
        int n0 = __ldg(&nbr[j]);
        int n1 = __ldg(&nbr[j + 1]);
        int n2 = __ldg(&nbr[j + 2]);
        int n3 = __ldg(&nbr[j + 3]);
        uint4 p0 = src[(size_t)n0 * LPG + lane];
        uint4 p1 = src[(size_t)n1 * LPG + lane];
        uint4 p2 = src[(size_t)n2 * LPG + lane];
        uint4 p3 = src[(size_t)n3 * LPG + lane];
        const __half2* h0 = (const __half2*)&p0;
        const __half2* h1 = (const __half2*)&p1;
        const __half2* h2 = (const __half2*)&p2;
        const __half2* h3 = (const __half2*)&p3;
        #pragma unroll
        for (int i = 0; i < 4; i++) {
            float2 a = __half22float2(h0[i]);
            float2 b = __half22float2(h1[i]);
            float2 c = __half22float2(h2[i]);
            float2 d = __half22float2(h3[i]);
            acc0[i].x += a.x + b.x;
            acc0[i].y += a.y + b.y;
            acc1[i].x += c.x + d.x;
            acc1[i].y += c.y + d.y;
        }
    }
    for (; j < s1; j++) {
        int n0 = __ldg(&nbr[j]);
        uint4 p0 = src[(size_t)n0 * LPG + lane];
        const __half2* h0 = (const __half2*)&p0;
        #pragma unroll
        for (int i = 0; i < 4; i++) {
            float2 a = __half22float2(h0[i]);
            acc0[i].x += a.x;
            acc0[i].y += a.y;
        }
    }
    float s = dscale[row];
    float v[8];
    #pragma unroll
    for (int i = 0; i < 4; i++) {
        v[2*i]   = (acc0[i].x + acc1[i].x) * s;
        v[2*i+1] = (acc0[i].y + acc1[i].y) * s;
    }
    if (HF_OUT) {
        uint4 outw;
        __half2* oh = (__half2*)&outw;
        #pragma unroll
        for (int i = 0; i < 4; i++)
            oh[i] = __floats2half2_rn(v[2*i], v[2*i+1]);
        ((uint4*)dst)[(size_t)row * LPG + lane] = outw;
    } else {
        const float* bp = bias + lane * 8;
        #pragma unroll
        for (int i = 0; i < 8; i++) v[i] += bp[i];
        if (do_elu) {
            #pragma unroll
            for (int i = 0; i < 8; i++) v[i] = v[i] > 0.f ? v[i] : expm1f(v[i]);
        }
        float4* dp = (float4*)dst + (size_t)row * (LPG * 2) + lane * 2;
        dp[0] = make_float4(v[0], v[1], v[2], v[3]);
        dp[1] = make_float4(v[4], v[5], v[6], v[7]);
    }
}

// ---------------- host driver ----------------
static inline int cdiv(int a, int b) { return (a + b - 1) / b; }

extern "C" void kernel_launch(void* const* d_in, const int* in_sizes, int n_in,
                              void* d_out, int out_size) {
    const float* x  = (const float*)d_in[0];
    const void*  ei = d_in[1];
    const float* W1 = (const float*)d_in[3];
    const float* b1 = (const float*)d_in[4];
    const float* W2 = (const float*)d_in[5];
    const float* b2 = (const float*)d_in[6];
    const float* W3 = (const float*)d_in[7];
    const float* b3 = (const float*)d_in[8];

    float *A, *B, *C, *inv_v, *inv_e;
    int *cnt_v, *cnt_e, *cur_v, *cur_e, *off_v, *off_e, *nbr_v, *nbr_e;
    cudaGetSymbolAddress((void**)&A, g_bufA);
    cudaGetSymbolAddress((void**)&B, g_bufB);
    cudaGetSymbolAddress((void**)&C, g_bufC);
    cudaGetSymbolAddress((void**)&inv_v, g_inv_v);
    cudaGetSymbolAddress((void**)&inv_e, g_inv_e);
    cudaGetSymbolAddress((void**)&cnt_v, g_cnt_v);
    cudaGetSymbolAddress((void**)&cnt_e, g_cnt_e);
    cudaGetSymbolAddress((void**)&cur_v, g_cur_v);
    cudaGetSymbolAddress((void**)&cur_e, g_cur_e);
    cudaGetSymbolAddress((void**)&off_v, g_off_v);
    cudaGetSymbolAddress((void**)&off_e, g_off_e);
    cudaGetSymbolAddress((void**)&nbr_v, g_nbr_v);
    cudaGetSymbolAddress((void**)&nbr_e, g_nbr_e);

    const int TB = 256;

    k_zero_i<<<cdiv(N_NODES, TB), TB>>>(cnt_v, N_NODES);
    k_zero_i<<<cdiv(N_HEDGES, TB), TB>>>(cnt_e, N_HEDGES);
    k_zero_i<<<cdiv(N_NODES, TB), TB>>>(cur_v, N_NODES);
    k_zero_i<<<cdiv(N_HEDGES, TB), TB>>>(cur_e, N_HEDGES);
    k_detect<<<1, 32>>>((const int*)ei);
    k_convert<<<cdiv(NNZ, TB), TB>>>(ei);
    k_scan<<<2, 1024>>>();
    k_fill<<<cdiv(NNZ, TB), TB>>>();
    k_invdeg<<<cdiv(N_NODES, TB), TB>>>();

    auto layer = [&](const float* hin, const float* W, const float* bias,
                     float* hout, int Cin, int Cout, int elu) {
        __half* msg = (__half*)A;
        __half* xe  = (__half*)B;
        dim3 gg(Cout / 128, cdiv(N_NODES, 128));
        k_tgemm<<<gg, 256>>>(hin, W, msg, N_NODES, Cin, Cout);
        if (Cout == 256) {
            k_gather<32, 8, 1><<<cdiv(N_HEDGES, 8), 256>>>(
                (const uint4*)msg, off_e, nbr_e, inv_e, nullptr,
                xe, N_HEDGES, 0);
            k_gather<32, 8, 0><<<cdiv(N_NODES, 8), 256>>>(
                (const uint4*)xe, off_v, nbr_v, inv_v, bias,
                hout, N_NODES, elu);
        } else {
            k_gather<16, 16, 1><<<cdiv(N_HEDGES, 16), 256>>>(
                (const uint4*)msg, off_e, nbr_e, inv_e, nullptr,
                xe, N_HEDGES, 0);
            k_gather<16, 16, 0><<<cdiv(N_NODES, 16), 256>>>(
                (const uint4*)xe, off_v, nbr_v, inv_v, bias,
                hout, N_NODES, elu);
        }
    };

    float* out = (float*)d_out;

    layer(x, W1, b1, C, F_IN, HID, 1);
    layer(C, W2, b2, C, HID, HID, 1);
    layer(C, W3, b3, out, HID, F_OUT, 0);
}

// round 8
// speedup vs baseline: 1.1326x; 1.1326x over previous
#include <cuda_runtime.h>
#include <cuda_fp16.h>
#include <cstdint>
#include <math.h>

#define N_NODES  50000
#define N_HEDGES 50000
#define NNZ      800000
#define F_IN     256
#define HID      256
#define F_OUT    128

// ---------------- scratch (device globals; no allocs allowed) ----------------
__device__ __align__(128) float g_bufA[N_NODES * HID];  // msg (fp16, reinterpreted)
__device__ __align__(128) float g_bufB[N_NODES * HID];  // xe  (fp16, reinterpreted)
__device__ __align__(128) float g_bufC[N_NODES * HID];  // h   (fp32)
__device__ __align__(128) float g_inv_v[N_NODES];
__device__ __align__(128) float g_inv_e[N_HEDGES];
__device__ __align__(128) int   g_cnt_v[N_NODES];
__device__ __align__(128) int   g_cnt_e[N_HEDGES];
__device__ __align__(128) int   g_cur_v[N_NODES];
__device__ __align__(128) int   g_cur_e[N_HEDGES];
__device__ __align__(128) int   g_off_v[N_NODES + 1];
__device__ __align__(128) int   g_off_e[N_HEDGES + 1];
__device__ __align__(128) int   g_vi[NNZ];
__device__ __align__(128) int   g_hi[NNZ];
__device__ __align__(128) int   g_nbr_e[NNZ];
__device__ __align__(128) int   g_nbr_v[NNZ];
__device__ int g_flag[1];

// ---------------- small utility kernels ----------------
// Zero all 4 count/cursor arrays in one launch.
__global__ void k_zero_all() {
    int i = blockIdx.x * blockDim.x + threadIdx.x;
    if (i < N_NODES)  { g_cnt_v[i] = 0; g_cur_v[i] = 0; }
    if (i < N_HEDGES) { g_cnt_e[i] = 0; g_cur_e[i] = 0; }
}

__global__ void k_detect(const int* __restrict__ ei) {
    if (blockIdx.x == 0 && threadIdx.x == 0) {
        int z = 0;
        #pragma unroll
        for (int i = 1; i < 64; i += 2) z |= ei[i];
        g_flag[0] = (z == 0) ? 1 : 0;
    }
}

__global__ void k_convert(const void* __restrict__ ei_raw) {
    int i = blockIdx.x * blockDim.x + threadIdx.x;
    if (i >= NNZ) return;
    int v, h;
    if (g_flag[0]) {
        const long long* e = (const long long*)ei_raw;
        v = (int)e[i];
        h = (int)e[NNZ + i];
    } else {
        const int* e = (const int*)ei_raw;
        v = e[i];
        h = e[NNZ + i];
    }
    g_vi[i] = v;
    g_hi[i] = h;
    atomicAdd(&g_cnt_v[v], 1);
    atomicAdd(&g_cnt_e[h], 1);
}

__global__ void k_invdeg() {
    int i = blockIdx.x * blockDim.x + threadIdx.x;
    if (i < N_NODES)  g_inv_v[i] = 1.0f / (float)max(g_cnt_v[i], 1);
    if (i < N_HEDGES) g_inv_e[i] = 1.0f / (float)max(g_cnt_e[i], 1);
}

__global__ void k_scan() {
    const int n = 50000;
    const int* cnt = blockIdx.x ? g_cnt_v : g_cnt_e;
    int* off       = blockIdx.x ? g_off_v : g_off_e;
    __shared__ int partial[1024];
    int t = threadIdx.x;
    const int PER = (n + 1023) / 1024;
    int base = t * PER;
    int s = 0;
    for (int i = 0; i < PER; i++) {
        int idx = base + i;
        if (idx < n) s += cnt[idx];
    }
    partial[t] = s;
    __syncthreads();
    for (int d = 1; d < 1024; d <<= 1) {
        int v = (t >= d) ? partial[t - d] : 0;
        __syncthreads();
        partial[t] += v;
        __syncthreads();
    }
    int run = (t == 0) ? 0 : partial[t - 1];
    for (int i = 0; i < PER; i++) {
        int idx = base + i;
        if (idx < n) { off[idx] = run; run += cnt[idx]; }
    }
    if (t == 1023) off[n] = run;
}

__global__ void k_fill() {
    int i = blockIdx.x * blockDim.x + threadIdx.x;
    if (i >= NNZ) return;
    int v = g_vi[i], h = g_hi[i];
    int pe = g_off_e[h] + atomicAdd(&g_cur_e[h], 1);
    g_nbr_e[pe] = v;
    int pv = g_off_v[v] + atomicAdd(&g_cur_v[v], 1);
    g_nbr_v[pv] = h;
}

// ---------------- TF32 tensor-core GEMM, fp16 output ----------------
__device__ __forceinline__ uint32_t f2tf32(float x) {
    uint32_t r;
    asm("cvt.rna.tf32.f32 %0, %1;" : "=r"(r) : "f"(x));
    return r;
}

__global__ __launch_bounds__(256, 2)
void k_tgemm(const float* __restrict__ A, const float* __restrict__ B,
             __half* __restrict__ C, int M, int K, int N) {
    __shared__ uint32_t As[2][8][132];
    __shared__ uint32_t Bs[2][8][132];
    const int t = threadIdx.x;
    const int lane = t & 31;
    const int warp = t >> 5;
    const int warp_m = (warp & 1) * 64;
    const int warp_n = (warp >> 1) * 32;
    const int gid = lane >> 2;
    const int tg  = lane & 3;

    const int arow = t >> 1, acol = (t & 1) * 4;
    const int brow = t >> 5, bcol = (t & 31) * 4;
    const int bm = blockIdx.y * 128, bn = blockIdx.x * 128;
    const bool arow_ok = (bm + arow) < M;
    const float* Ap = A + (size_t)(bm + arow) * K + acol;
    const float* Bp = B + (size_t)brow * N + bn + bcol;

    float acc[4][4][4] = {};
    float4 aReg, bReg;

    aReg = arow_ok ? *(const float4*)Ap : make_float4(0.f, 0.f, 0.f, 0.f);
    bReg = *(const float4*)Bp;
    As[0][acol + 0][arow] = f2tf32(aReg.x);
    As[0][acol + 1][arow] = f2tf32(aReg.y);
    As[0][acol + 2][arow] = f2tf32(aReg.z);
    As[0][acol + 3][arow] = f2tf32(aReg.w);
    Bs[0][brow][bcol + 0] = f2tf32(bReg.x);
    Bs[0][brow][bcol + 1] = f2tf32(bReg.y);
    Bs[0][brow][bcol + 2] = f2tf32(bReg.z);
    Bs[0][brow][bcol + 3] = f2tf32(bReg.w);
    __syncthreads();

    const int nk = K >> 3;
    for (int kt = 0; kt < nk; kt++) {
        const int cur = kt & 1, nxt = cur ^ 1;
        if (kt + 1 < nk) {
            aReg = arow_ok ? *(const float4*)(Ap + (kt + 1) * 8)
                           : make_float4(0.f, 0.f, 0.f, 0.f);
            bReg = *(const float4*)(Bp + (size_t)(kt + 1) * 8 * N);
        }

        uint32_t af[4][4], bf[4][2];
        #pragma unroll
        for (int mt = 0; mt < 4; mt++) {
            int r = warp_m + mt * 16 + gid;
            af[mt][0] = As[cur][tg][r];
            af[mt][1] = As[cur][tg][r + 8];
            af[mt][2] = As[cur][tg + 4][r];
            af[mt][3] = As[cur][tg + 4][r + 8];
        }
        #pragma unroll
        for (int nt = 0; nt < 4; nt++) {
            int c = warp_n + nt * 8 + gid;
            bf[nt][0] = Bs[cur][tg][c];
            bf[nt][1] = Bs[cur][tg + 4][c];
        }
        #pragma unroll
        for (int mt = 0; mt < 4; mt++)
            #pragma unroll
            for (int nt = 0; nt < 4; nt++) {
                asm volatile(
                    "mma.sync.aligned.m16n8k8.row.col.f32.tf32.tf32.f32 "
                    "{%0,%1,%2,%3}, {%4,%5,%6,%7}, {%8,%9}, {%0,%1,%2,%3};"
                    : "+f"(acc[mt][nt][0]), "+f"(acc[mt][nt][1]),
                      "+f"(acc[mt][nt][2]), "+f"(acc[mt][nt][3])
                    : "r"(af[mt][0]), "r"(af[mt][1]), "r"(af[mt][2]), "r"(af[mt][3]),
                      "r"(bf[nt][0]), "r"(bf[nt][1]));
            }

        if (kt + 1 < nk) {
            As[nxt][acol + 0][arow] = f2tf32(aReg.x);
            As[nxt][acol + 1][arow] = f2tf32(aReg.y);
            As[nxt][acol + 2][arow] = f2tf32(aReg.z);
            As[nxt][acol + 3][arow] = f2tf32(aReg.w);
            Bs[nxt][brow][bcol + 0] = f2tf32(bReg.x);
            Bs[nxt][brow][bcol + 1] = f2tf32(bReg.y);
            Bs[nxt][brow][bcol + 2] = f2tf32(bReg.z);
            Bs[nxt][brow][bcol + 3] = f2tf32(bReg.w);
        }
        __syncthreads();
    }

    #pragma unroll
    for (int mt = 0; mt < 4; mt++) {
        int r0 = bm + warp_m + mt * 16 + gid;
        #pragma unroll
        for (int nt = 0; nt < 4; nt++) {
            int c0 = bn + warp_n + nt * 8 + tg * 2;
            if (r0 < M)
                *(__half2*)&C[(size_t)r0 * N + c0] =
                    __floats2half2_rn(acc[mt][nt][0], acc[mt][nt][1]);
            if (r0 + 8 < M)
                *(__half2*)&C[(size_t)(r0 + 8) * N + c0] =
                    __floats2half2_rn(acc[mt][nt][2], acc[mt][nt][3]);
        }
    }
}

// ---------------- CSR gathers over fp16 rows ----------------
// Unroll-2 with HADD2 pre-add of the neighbor pair, fp32 accumulation.
template<int LPG, int RPB, int HF_OUT>
__global__ __launch_bounds__(LPG * RPB)
void k_gather(const uint4* __restrict__ src,
              const int* __restrict__ off,
              const int* __restrict__ nbr,
              const float* __restrict__ dscale,
              const float* __restrict__ bias,
              void* __restrict__ dst, int nrows, int do_elu) {
    const int group = threadIdx.x / LPG;
    const int lane  = threadIdx.x % LPG;
    const int row = blockIdx.x * RPB + group;
    if (row >= nrows) return;
    const int s0 = off[row], s1 = off[row + 1];

    float2 acc[4] = {};
    int j = s0;
    for (; j + 1 < s1; j += 2) {
        int n0 = __ldg(&nbr[j]);
        int n1 = __ldg(&nbr[j + 1]);
        uint4 p0 = src[(size_t)n0 * LPG + lane];
        uint4 p1 = src[(size_t)n1 * LPG + lane];
        const __half2* h0 = (const __half2*)&p0;
        const __half2* h1 = (const __half2*)&p1;
        #pragma unroll
        for (int i = 0; i < 4; i++) {
            float2 f = __half22float2(__hadd2(h0[i], h1[i]));
            acc[i].x += f.x;
            acc[i].y += f.y;
        }
    }
    if (j < s1) {
        int n0 = __ldg(&nbr[j]);
        uint4 p0 = src[(size_t)n0 * LPG + lane];
        const __half2* h0 = (const __half2*)&p0;
        #pragma unroll
        for (int i = 0; i < 4; i++) {
            float2 a = __half22float2(h0[i]);
            acc[i].x += a.x;
            acc[i].y += a.y;
        }
    }
    float s = dscale[row];
    float v[8];
    #pragma unroll
    for (int i = 0; i < 4; i++) {
        v[2*i]   = acc[i].x * s;
        v[2*i+1] = acc[i].y * s;
    }
    if (HF_OUT) {
        uint4 outw;
        __half2* oh = (__half2*)&outw;
        #pragma unroll
        for (int i = 0; i < 4; i++)
            oh[i] = __floats2half2_rn(v[2*i], v[2*i+1]);
        ((uint4*)dst)[(size_t)row * LPG + lane] = outw;
    } else {
        const float* bp = bias + lane * 8;
        #pragma unroll
        for (int i = 0; i < 8; i++) v[i] += bp[i];
        if (do_elu) {
            #pragma unroll
            for (int i = 0; i < 8; i++) v[i] = v[i] > 0.f ? v[i] : expm1f(v[i]);
        }
        float4* dp = (float4*)dst + (size_t)row * (LPG * 2) + lane * 2;
        dp[0] = make_float4(v[0], v[1], v[2], v[3]);
        dp[1] = make_float4(v[4], v[5], v[6], v[7]);
    }
}

// ---------------- host driver ----------------
static inline int cdiv(int a, int b) { return (a + b - 1) / b; }

extern "C" void kernel_launch(void* const* d_in, const int* in_sizes, int n_in,
                              void* d_out, int out_size) {
    const float* x  = (const float*)d_in[0];
    const void*  ei = d_in[1];
    const float* W1 = (const float*)d_in[3];
    const float* b1 = (const float*)d_in[4];
    const float* W2 = (const float*)d_in[5];
    const float* b2 = (const float*)d_in[6];
    const float* W3 = (const float*)d_in[7];
    const float* b3 = (const float*)d_in[8];

    float *A, *B, *C, *inv_v, *inv_e;
    int *off_v, *off_e, *nbr_v, *nbr_e;
    cudaGetSymbolAddress((void**)&A, g_bufA);
    cudaGetSymbolAddress((void**)&B, g_bufB);
    cudaGetSymbolAddress((void**)&C, g_bufC);
    cudaGetSymbolAddress((void**)&inv_v, g_inv_v);
    cudaGetSymbolAddress((void**)&inv_e, g_inv_e);
    cudaGetSymbolAddress((void**)&off_v, g_off_v);
    cudaGetSymbolAddress((void**)&off_e, g_off_e);
    cudaGetSymbolAddress((void**)&nbr_v, g_nbr_v);
    cudaGetSymbolAddress((void**)&nbr_e, g_nbr_e);

    const int TB = 256;

    k_zero_all<<<cdiv(N_NODES, TB), TB>>>();
    k_detect<<<1, 32>>>((const int*)ei);
    k_convert<<<cdiv(NNZ, TB), TB>>>(ei);
    k_scan<<<2, 1024>>>();
    k_fill<<<cdiv(NNZ, TB), TB>>>();
    k_invdeg<<<cdiv(N_NODES, TB), TB>>>();

    auto layer = [&](const float* hin, const float* W, const float* bias,
                     float* hout, int Cin, int Cout, int elu) {
        __half* msg = (__half*)A;
        __half* xe  = (__half*)B;
        dim3 gg(Cout / 128, cdiv(N_NODES, 128));
        k_tgemm<<<gg, 256>>>(hin, W, msg, N_NODES, Cin, Cout);
        if (Cout == 256) {
            k_gather<32, 8, 1><<<cdiv(N_HEDGES, 8), 256>>>(
                (const uint4*)msg, off_e, nbr_e, inv_e, nullptr,
                xe, N_HEDGES, 0);
            k_gather<32, 8, 0><<<cdiv(N_NODES, 8), 256>>>(
                (const uint4*)xe, off_v, nbr_v, inv_v, bias,
                hout, N_NODES, elu);
        } else {
            k_gather<16, 16, 1><<<cdiv(N_HEDGES, 16), 256>>>(
                (const uint4*)msg, off_e, nbr_e, inv_e, nullptr,
                xe, N_HEDGES, 0);
            k_gather<16, 16, 0><<<cdiv(N_NODES, 16), 256>>>(
                (const uint4*)xe, off_v, nbr_v, inv_v, bias,
                hout, N_NODES, elu);
        }
    };

    float* out = (float*)d_out;

    layer(x, W1, b1, C, F_IN, HID, 1);
    layer(C, W2, b2, C, HID, HID, 1);
    layer(C, W3, b3, out, HID, F_OUT, 0);
}

// round 9
// speedup vs baseline: 1.2458x; 1.0999x over previous
#include <cuda_runtime.h>
#include <cuda_fp16.h>
#include <cstdint>
#include <math.h>

#define N_NODES  50000
#define N_HEDGES 50000
#define NNZ      800000
#define F_IN     256
#define HID      256
#define F_OUT    128
#define NCHUNK   196   // ceil(50000/256)

// ---------------- scratch (device globals; no allocs allowed) ----------------
__device__ __align__(128) float g_bufA[N_NODES * HID];  // msg (fp16, reinterpreted)
__device__ __align__(128) float g_bufB[N_NODES * HID];  // xe  (fp16, reinterpreted)
__device__ __align__(128) float g_bufC[N_NODES * HID];  // h   (fp32)
__device__ __align__(128) float g_inv_v[N_NODES];
__device__ __align__(128) float g_inv_e[N_HEDGES];
__device__ __align__(128) int   g_cnt_v[N_NODES];
__device__ __align__(128) int   g_cnt_e[N_HEDGES];
__device__ __align__(128) int   g_cur_v[N_NODES];
__device__ __align__(128) int   g_cur_e[N_HEDGES];
__device__ __align__(128) int   g_off_v[N_NODES + 1];
__device__ __align__(128) int   g_off_e[N_HEDGES + 1];
__device__ __align__(128) int   g_vi[NNZ];
__device__ __align__(128) int   g_hi[NNZ];
__device__ __align__(128) int   g_nbr_e[NNZ];
__device__ __align__(128) int   g_nbr_v[NNZ];
__device__ __align__(128) int   g_bsum[2 * NCHUNK];
__device__ __align__(128) int   g_bbase[2 * NCHUNK];
__device__ int g_flag[1];

// ---------------- small utility kernels ----------------
__global__ void k_zero_all() {
    int i = blockIdx.x * blockDim.x + threadIdx.x;
    if (i < N_NODES)  { g_cnt_v[i] = 0; g_cur_v[i] = 0; }
    if (i < N_HEDGES) { g_cnt_e[i] = 0; g_cur_e[i] = 0; }
}

__global__ void k_detect(const int* __restrict__ ei) {
    if (blockIdx.x == 0 && threadIdx.x == 0) {
        int z = 0;
        #pragma unroll
        for (int i = 1; i < 64; i += 2) z |= ei[i];
        g_flag[0] = (z == 0) ? 1 : 0;
    }
}

__global__ void k_convert(const void* __restrict__ ei_raw) {
    int i = blockIdx.x * blockDim.x + threadIdx.x;
    if (i >= NNZ) return;
    int v, h;
    if (g_flag[0]) {
        const long long* e = (const long long*)ei_raw;
        v = (int)e[i];
        h = (int)e[NNZ + i];
    } else {
        const int* e = (const int*)ei_raw;
        v = e[i];
        h = e[NNZ + i];
    }
    g_vi[i] = v;
    g_hi[i] = h;
    atomicAdd(&g_cnt_v[v], 1);
    atomicAdd(&g_cnt_e[h], 1);
}

// ---------------- 3-phase scan (both arrays at once) ----------------
__device__ __forceinline__ int block_scan_incl(int val, int* warp_sums) {
    int lane = threadIdx.x & 31, w = threadIdx.x >> 5;
    #pragma unroll
    for (int d = 1; d < 32; d <<= 1) {
        int n = __shfl_up_sync(0xffffffffu, val, d);
        if (lane >= d) val += n;
    }
    if (lane == 31) warp_sums[w] = val;
    __syncthreads();
    if (w == 0) {
        int s = (lane < 8) ? warp_sums[lane] : 0;
        #pragma unroll
        for (int d = 1; d < 8; d <<= 1) {
            int n = __shfl_up_sync(0xffffffffu, s, d);
            if (lane >= d) s += n;
        }
        if (lane < 8) warp_sums[lane] = s;
    }
    __syncthreads();
    if (w > 0) val += warp_sums[w - 1];
    return val;
}

// Phase A: block-local exclusive scans; blocks [0,196)=e, [196,392)=v
__global__ void k_scanA() {
    __shared__ int ws[8];
    int arr = blockIdx.x / NCHUNK;
    int idx = (blockIdx.x % NCHUNK) * 256 + threadIdx.x;
    const int* cnt = arr ? g_cnt_v : g_cnt_e;
    int* off       = arr ? g_off_v : g_off_e;
    int val = (idx < 50000) ? cnt[idx] : 0;
    int incl = block_scan_incl(val, ws);
    if (idx < 50000) off[idx] = incl - val;
    if (threadIdx.x == 255) g_bsum[blockIdx.x] = incl;
}

// Phase B: scan the 196 block sums per array; write total to off[50000]
__global__ void k_scanB() {
    __shared__ int ws[8];
    int arr = blockIdx.x;
    int i = threadIdx.x;
    int val = (i < NCHUNK) ? g_bsum[arr * NCHUNK + i] : 0;
    int incl = block_scan_incl(val, ws);
    if (i < NCHUNK) g_bbase[arr * NCHUNK + i] = incl - val;
    if (i == NCHUNK - 1) (arr ? g_off_v : g_off_e)[50000] = incl;
}

// Phase C: add block bases; also compute inverse degrees (folds k_invdeg)
__global__ void k_scanC() {
    int arr = blockIdx.x / NCHUNK;
    int idx = (blockIdx.x % NCHUNK) * 256 + threadIdx.x;
    if (idx >= 50000) return;
    int base = g_bbase[blockIdx.x];
    if (arr) {
        g_off_v[idx] += base;
        g_inv_v[idx] = 1.0f / (float)max(g_cnt_v[idx], 1);
    } else {
        g_off_e[idx] += base;
        g_inv_e[idx] = 1.0f / (float)max(g_cnt_e[idx], 1);
    }
}

__global__ void k_fill() {
    int i = blockIdx.x * blockDim.x + threadIdx.x;
    if (i >= NNZ) return;
    int v = g_vi[i], h = g_hi[i];
    int pe = g_off_e[h] + atomicAdd(&g_cur_e[h], 1);
    g_nbr_e[pe] = v;
    int pv = g_off_v[v] + atomicAdd(&g_cur_v[v], 1);
    g_nbr_v[pv] = h;
}

// ---------------- TF32 tensor-core GEMM, fp16 output ----------------
__device__ __forceinline__ uint32_t f2tf32(float x) {
    uint32_t r;
    asm("cvt.rna.tf32.f32 %0, %1;" : "=r"(r) : "f"(x));
    return r;
}

__global__ __launch_bounds__(256, 2)
void k_tgemm(const float* __restrict__ A, const float* __restrict__ B,
             __half* __restrict__ C, int M, int K, int N) {
    __shared__ uint32_t As[2][8][132];
    __shared__ uint32_t Bs[2][8][132];
    const int t = threadIdx.x;
    const int lane = t & 31;
    const int warp = t >> 5;
    const int warp_m = (warp & 1) * 64;
    const int warp_n = (warp >> 1) * 32;
    const int gid = lane >> 2;
    const int tg  = lane & 3;

    const int arow = t >> 1, acol = (t & 1) * 4;
    const int brow = t >> 5, bcol = (t & 31) * 4;
    const int bm = blockIdx.y * 128, bn = blockIdx.x * 128;
    const bool arow_ok = (bm + arow) < M;
    const float* Ap = A + (size_t)(bm + arow) * K + acol;
    const float* Bp = B + (size_t)brow * N + bn + bcol;

    float acc[4][4][4] = {};
    float4 aReg, bReg;

    aReg = arow_ok ? *(const float4*)Ap : make_float4(0.f, 0.f, 0.f, 0.f);
    bReg = *(const float4*)Bp;
    As[0][acol + 0][arow] = f2tf32(aReg.x);
    As[0][acol + 1][arow] = f2tf32(aReg.y);
    As[0][acol + 2][arow] = f2tf32(aReg.z);
    As[0][acol + 3][arow] = f2tf32(aReg.w);
    Bs[0][brow][bcol + 0] = f2tf32(bReg.x);
    Bs[0][brow][bcol + 1] = f2tf32(bReg.y);
    Bs[0][brow][bcol + 2] = f2tf32(bReg.z);
    Bs[0][brow][bcol + 3] = f2tf32(bReg.w);
    __syncthreads();

    const int nk = K >> 3;
    for (int kt = 0; kt < nk; kt++) {
        const int cur = kt & 1, nxt = cur ^ 1;
        if (kt + 1 < nk) {
            aReg = arow_ok ? *(const float4*)(Ap + (kt + 1) * 8)
                           : make_float4(0.f, 0.f, 0.f, 0.f);
            bReg = *(const float4*)(Bp + (size_t)(kt + 1) * 8 * N);
        }

        uint32_t af[4][4], bf[4][2];
        #pragma unroll
        for (int mt = 0; mt < 4; mt++) {
            int r = warp_m + mt * 16 + gid;
            af[mt][0] = As[cur][tg][r];
            af[mt][1] = As[cur][tg][r + 8];
            af[mt][2] = As[cur][tg + 4][r];
            af[mt][3] = As[cur][tg + 4][r + 8];
        }
        #pragma unroll
        for (int nt = 0; nt < 4; nt++) {
            int c = warp_n + nt * 8 + gid;
            bf[nt][0] = Bs[cur][tg][c];
            bf[nt][1] = Bs[cur][tg + 4][c];
        }
        #pragma unroll
        for (int mt = 0; mt < 4; mt++)
            #pragma unroll
            for (int nt = 0; nt < 4; nt++) {
                asm volatile(
                    "mma.sync.aligned.m16n8k8.row.col.f32.tf32.tf32.f32 "
                    "{%0,%1,%2,%3}, {%4,%5,%6,%7}, {%8,%9}, {%0,%1,%2,%3};"
                    : "+f"(acc[mt][nt][0]), "+f"(acc[mt][nt][1]),
                      "+f"(acc[mt][nt][2]), "+f"(acc[mt][nt][3])
                    : "r"(af[mt][0]), "r"(af[mt][1]), "r"(af[mt][2]), "r"(af[mt][3]),
                      "r"(bf[nt][0]), "r"(bf[nt][1]));
            }

        if (kt + 1 < nk) {
            As[nxt][acol + 0][arow] = f2tf32(aReg.x);
            As[nxt][acol + 1][arow] = f2tf32(aReg.y);
            As[nxt][acol + 2][arow] = f2tf32(aReg.z);
            As[nxt][acol + 3][arow] = f2tf32(aReg.w);
            Bs[nxt][brow][bcol + 0] = f2tf32(bReg.x);
            Bs[nxt][brow][bcol + 1] = f2tf32(bReg.y);
            Bs[nxt][brow][bcol + 2] = f2tf32(bReg.z);
            Bs[nxt][brow][bcol + 3] = f2tf32(bReg.w);
        }
        __syncthreads();
    }

    #pragma unroll
    for (int mt = 0; mt < 4; mt++) {
        int r0 = bm + warp_m + mt * 16 + gid;
        #pragma unroll
        for (int nt = 0; nt < 4; nt++) {
            int c0 = bn + warp_n + nt * 8 + tg * 2;
            if (r0 < M)
                *(__half2*)&C[(size_t)r0 * N + c0] =
                    __floats2half2_rn(acc[mt][nt][0], acc[mt][nt][1]);
            if (r0 + 8 < M)
                *(__half2*)&C[(size_t)(r0 + 8) * N + c0] =
                    __floats2half2_rn(acc[mt][nt][2], acc[mt][nt][3]);
        }
    }
}

// ---------------- CSR gathers over fp16 rows ----------------
template<int LPG, int RPB, int HF_OUT>
__global__ __launch_bounds__(LPG * RPB)
void k_gather(const uint4* __restrict__ src,
              const int* __restrict__ off,
              const int* __restrict__ nbr,
              const float* __restrict__ dscale,
              const float* __restrict__ bias,
              void* __restrict__ dst, int nrows, int do_elu) {
    const int group = threadIdx.x / LPG;
    const int lane  = threadIdx.x % LPG;
    const int row = blockIdx.x * RPB + group;
    if (row >= nrows) return;
    const int s0 = off[row], s1 = off[row + 1];

    float2 acc[4] = {};
    int j = s0;
    for (; j + 1 < s1; j += 2) {
        int n0 = __ldg(&nbr[j]);
        int n1 = __ldg(&nbr[j + 1]);
        uint4 p0 = src[(size_t)n0 * LPG + lane];
        uint4 p1 = src[(size_t)n1 * LPG + lane];
        const __half2* h0 = (const __half2*)&p0;
        const __half2* h1 = (const __half2*)&p1;
        #pragma unroll
        for (int i = 0; i < 4; i++) {
            float2 f = __half22float2(__hadd2(h0[i], h1[i]));
            acc[i].x += f.x;
            acc[i].y += f.y;
        }
    }
    if (j < s1) {
        int n0 = __ldg(&nbr[j]);
        uint4 p0 = src[(size_t)n0 * LPG + lane];
        const __half2* h0 = (const __half2*)&p0;
        #pragma unroll
        for (int i = 0; i < 4; i++) {
            float2 a = __half22float2(h0[i]);
            acc[i].x += a.x;
            acc[i].y += a.y;
        }
    }
    float s = dscale[row];
    float v[8];
    #pragma unroll
    for (int i = 0; i < 4; i++) {
        v[2*i]   = acc[i].x * s;
        v[2*i+1] = acc[i].y * s;
    }
    if (HF_OUT) {
        uint4 outw;
        __half2* oh = (__half2*)&outw;
        #pragma unroll
        for (int i = 0; i < 4; i++)
            oh[i] = __floats2half2_rn(v[2*i], v[2*i+1]);
        ((uint4*)dst)[(size_t)row * LPG + lane] = outw;
    } else {
        const float* bp = bias + lane * 8;
        #pragma unroll
        for (int i = 0; i < 8; i++) v[i] += bp[i];
        if (do_elu) {
            #pragma unroll
            for (int i = 0; i < 8; i++) v[i] = v[i] > 0.f ? v[i] : expm1f(v[i]);
        }
        float4* dp = (float4*)dst + (size_t)row * (LPG * 2) + lane * 2;
        dp[0] = make_float4(v[0], v[1], v[2], v[3]);
        dp[1] = make_float4(v[4], v[5], v[6], v[7]);
    }
}

// ---------------- host driver ----------------
static inline int cdiv(int a, int b) { return (a + b - 1) / b; }

extern "C" void kernel_launch(void* const* d_in, const int* in_sizes, int n_in,
                              void* d_out, int out_size) {
    const float* x  = (const float*)d_in[0];
    const void*  ei = d_in[1];
    const float* W1 = (const float*)d_in[3];
    const float* b1 = (const float*)d_in[4];
    const float* W2 = (const float*)d_in[5];
    const float* b2 = (const float*)d_in[6];
    const float* W3 = (const float*)d_in[7];
    const float* b3 = (const float*)d_in[8];

    float *A, *B, *C, *inv_v, *inv_e;
    int *off_v, *off_e, *nbr_v, *nbr_e;
    cudaGetSymbolAddress((void**)&A, g_bufA);
    cudaGetSymbolAddress((void**)&B, g_bufB);
    cudaGetSymbolAddress((void**)&C, g_bufC);
    cudaGetSymbolAddress((void**)&inv_v, g_inv_v);
    cudaGetSymbolAddress((void**)&inv_e, g_inv_e);
    cudaGetSymbolAddress((void**)&off_v, g_off_v);
    cudaGetSymbolAddress((void**)&off_e, g_off_e);
    cudaGetSymbolAddress((void**)&nbr_v, g_nbr_v);
    cudaGetSymbolAddress((void**)&nbr_e, g_nbr_e);

    const int TB = 256;

    k_zero_all<<<cdiv(N_NODES, TB), TB>>>();
    k_detect<<<1, 32>>>((const int*)ei);
    k_convert<<<cdiv(NNZ, TB), TB>>>(ei);
    k_scanA<<<2 * NCHUNK, 256>>>();
    k_scanB<<<2, 256>>>();
    k_scanC<<<2 * NCHUNK, 256>>>();
    k_fill<<<cdiv(NNZ, TB), TB>>>();

    auto layer = [&](const float* hin, const float* W, const float* bias,
                     float* hout, int Cin, int Cout, int elu) {
        __half* msg = (__half*)A;
        __half* xe  = (__half*)B;
        dim3 gg(Cout / 128, cdiv(N_NODES, 128));
        k_tgemm<<<gg, 256>>>(hin, W, msg, N_NODES, Cin, Cout);
        if (Cout == 256) {
            k_gather<32, 8, 1><<<cdiv(N_HEDGES, 8), 256>>>(
                (const uint4*)msg, off_e, nbr_e, inv_e, nullptr,
                xe, N_HEDGES, 0);
            k_gather<32, 8, 0><<<cdiv(N_NODES, 8), 256>>>(
                (const uint4*)xe, off_v, nbr_v, inv_v, bias,
                hout, N_NODES, elu);
        } else {
            k_gather<16, 16, 1><<<cdiv(N_HEDGES, 16), 256>>>(
                (const uint4*)msg, off_e, nbr_e, inv_e, nullptr,
                xe, N_HEDGES, 0);
            k_gather<16, 16, 0><<<cdiv(N_NODES, 16), 256>>>(
                (const uint4*)xe, off_v, nbr_v, inv_v, bias,
                hout, N_NODES, elu);
        }
    };

    float* out = (float*)d_out;

    layer(x, W1, b1, C, F_IN, HID, 1);
    layer(C, W2, b2, C, HID, HID, 1);
    layer(C, W3, b3, out, HID, F_OUT, 0);
}

// round 10
// speedup vs baseline: 1.4778x; 1.1862x over previous
#include <cuda_runtime.h>
#include <cuda_fp16.h>
#include <cstdint>
#include <math.h>

#define N_NODES  50000
#define N_HEDGES 50000
#define NNZ      800000
#define F_IN     256
#define HID      256
#define F_OUT    128
#define NCHUNK   196   // ceil(50000/256)

// ---------------- scratch (device globals; no allocs allowed) ----------------
__device__ __align__(128) float g_bufA[N_NODES * HID];  // msg (fp16, reinterpreted)
__device__ __align__(128) float g_bufB[N_NODES * HID];  // xe  (fp16, reinterpreted)
__device__ __align__(128) float g_bufC[N_NODES * HID];  // h   (fp32)
__device__ __align__(128) float g_inv_v[N_NODES];
__device__ __align__(128) float g_inv_e[N_HEDGES];
__device__ __align__(128) int   g_cnt_v[N_NODES];
__device__ __align__(128) int   g_cnt_e[N_HEDGES];
__device__ __align__(128) int   g_cur_v[N_NODES];
__device__ __align__(128) int   g_cur_e[N_HEDGES];
__device__ __align__(128) int   g_off_v[N_NODES + 1];
__device__ __align__(128) int   g_off_e[N_HEDGES + 1];
__device__ __align__(128) int   g_vi[NNZ];
__device__ __align__(128) int   g_hi[NNZ];
__device__ __align__(128) int   g_nbr_e[NNZ];
__device__ __align__(128) int   g_nbr_v[NNZ];
__device__ __align__(128) int   g_bsum[2 * NCHUNK];
__device__ __align__(128) int   g_bbase[2 * NCHUNK];
__device__ int g_flag[1];

// ---------------- small utility kernels ----------------
__global__ void k_zero_all() {
    int i = blockIdx.x * blockDim.x + threadIdx.x;
    if (i < N_NODES)  { g_cnt_v[i] = 0; g_cur_v[i] = 0; }
    if (i < N_HEDGES) { g_cnt_e[i] = 0; g_cur_e[i] = 0; }
}

__global__ void k_detect(const int* __restrict__ ei) {
    if (blockIdx.x == 0 && threadIdx.x == 0) {
        int z = 0;
        #pragma unroll
        for (int i = 1; i < 64; i += 2) z |= ei[i];
        g_flag[0] = (z == 0) ? 1 : 0;
    }
}

__global__ void k_convert(const void* __restrict__ ei_raw) {
    int i = blockIdx.x * blockDim.x + threadIdx.x;
    if (i >= NNZ) return;
    int v, h;
    if (g_flag[0]) {
        const long long* e = (const long long*)ei_raw;
        v = (int)e[i];
        h = (int)e[NNZ + i];
    } else {
        const int* e = (const int*)ei_raw;
        v = e[i];
        h = e[NNZ + i];
    }
    g_vi[i] = v;
    g_hi[i] = h;
    atomicAdd(&g_cnt_v[v], 1);
    atomicAdd(&g_cnt_e[h], 1);
}

// ---------------- 3-phase scan (both arrays at once) ----------------
__device__ __forceinline__ int block_scan_incl(int val, int* warp_sums) {
    int lane = threadIdx.x & 31, w = threadIdx.x >> 5;
    #pragma unroll
    for (int d = 1; d < 32; d <<= 1) {
        int n = __shfl_up_sync(0xffffffffu, val, d);
        if (lane >= d) val += n;
    }
    if (lane == 31) warp_sums[w] = val;
    __syncthreads();
    if (w == 0) {
        int s = (lane < 8) ? warp_sums[lane] : 0;
        #pragma unroll
        for (int d = 1; d < 8; d <<= 1) {
            int n = __shfl_up_sync(0xffffffffu, s, d);
            if (lane >= d) s += n;
        }
        if (lane < 8) warp_sums[lane] = s;
    }
    __syncthreads();
    if (w > 0) val += warp_sums[w - 1];
    return val;
}

__global__ void k_scanA() {
    __shared__ int ws[8];
    int arr = blockIdx.x / NCHUNK;
    int idx = (blockIdx.x % NCHUNK) * 256 + threadIdx.x;
    const int* cnt = arr ? g_cnt_v : g_cnt_e;
    int* off       = arr ? g_off_v : g_off_e;
    int val = (idx < 50000) ? cnt[idx] : 0;
    int incl = block_scan_incl(val, ws);
    if (idx < 50000) off[idx] = incl - val;
    if (threadIdx.x == 255) g_bsum[blockIdx.x] = incl;
}

__global__ void k_scanB() {
    __shared__ int ws[8];
    int arr = blockIdx.x;
    int i = threadIdx.x;
    int val = (i < NCHUNK) ? g_bsum[arr * NCHUNK + i] : 0;
    int incl = block_scan_incl(val, ws);
    if (i < NCHUNK) g_bbase[arr * NCHUNK + i] = incl - val;
    if (i == NCHUNK - 1) (arr ? g_off_v : g_off_e)[50000] = incl;
}

__global__ void k_scanC() {
    int arr = blockIdx.x / NCHUNK;
    int idx = (blockIdx.x % NCHUNK) * 256 + threadIdx.x;
    if (idx >= 50000) return;
    int base = g_bbase[blockIdx.x];
    if (arr) {
        g_off_v[idx] += base;
        g_inv_v[idx] = 1.0f / (float)max(g_cnt_v[idx], 1);
    } else {
        g_off_e[idx] += base;
        g_inv_e[idx] = 1.0f / (float)max(g_cnt_e[idx], 1);
    }
}

__global__ void k_fill() {
    int i = blockIdx.x * blockDim.x + threadIdx.x;
    if (i >= NNZ) return;
    int v = g_vi[i], h = g_hi[i];
    int pe = g_off_e[h] + atomicAdd(&g_cur_e[h], 1);
    g_nbr_e[pe] = v;
    int pv = g_off_v[v] + atomicAdd(&g_cur_v[v], 1);
    g_nbr_v[pv] = h;
}

// ---------------- FP16 tensor-core GEMM (fp32 accum), fp16 output -----------
// Block 128x128, k-chunk 16, 8 warps (2x4), warp tile 64x32, mma.m16n8k16.
// Smem holds k-adjacent half2 pairs: As2[k/2][m], Bs2[k/2][n].
__global__ __launch_bounds__(256, 2)
void k_hgemm(const float* __restrict__ A, const float* __restrict__ B,
             __half* __restrict__ C, int M, int K, int N) {
    __shared__ uint32_t As2[2][8][132];
    __shared__ uint32_t Bs2[2][8][132];
    const int t = threadIdx.x;
    const int lane = t & 31;
    const int warp = t >> 5;
    const int warp_m = (warp & 1) * 64;
    const int warp_n = (warp >> 1) * 32;
    const int gid = lane >> 2;
    const int tg  = lane & 3;

    // A loader: row = t>>1, 8 cols starting at (t&1)*8
    const int arow = t >> 1, acol = (t & 1) * 8;
    const int ak2  = acol >> 1;            // 0 or 4
    // B loader: k-pair t>>5, 4 cols starting at (t&31)*4
    const int bk2 = t >> 5, bn4 = (t & 31) * 4;

    const int bm = blockIdx.y * 128, bn = blockIdx.x * 128;
    const bool arow_ok = (bm + arow) < M;
    const float* Ap  = A + (size_t)(bm + arow) * K + acol;
    const float* Bp0 = B + (size_t)(2 * bk2) * N + bn + bn4;
    const float* Bp1 = Bp0 + N;

    float acc[4][4][4] = {};
    float4 a0, a1, u0, u1;

    a0 = arow_ok ? *(const float4*)Ap : make_float4(0.f, 0.f, 0.f, 0.f);
    a1 = arow_ok ? *(const float4*)(Ap + 4) : make_float4(0.f, 0.f, 0.f, 0.f);
    u0 = *(const float4*)Bp0;
    u1 = *(const float4*)Bp1;
    As2[0][ak2 + 0][arow] = __half2_raw(__floats2half2_rn(a0.x, a0.y)).x
                            | ((uint32_t)__half2_raw(__floats2half2_rn(a0.x, a0.y)).y << 16);
    // (use simpler direct reinterpretation below instead)
    {
        __half2 h;
        h = __floats2half2_rn(a0.x, a0.y); As2[0][ak2 + 0][arow] = *(uint32_t*)&h;
        h = __floats2half2_rn(a0.z, a0.w); As2[0][ak2 + 1][arow] = *(uint32_t*)&h;
        h = __floats2half2_rn(a1.x, a1.y); As2[0][ak2 + 2][arow] = *(uint32_t*)&h;
        h = __floats2half2_rn(a1.z, a1.w); As2[0][ak2 + 3][arow] = *(uint32_t*)&h;
        h = __floats2half2_rn(u0.x, u1.x); Bs2[0][bk2][bn4 + 0] = *(uint32_t*)&h;
        h = __floats2half2_rn(u0.y, u1.y); Bs2[0][bk2][bn4 + 1] = *(uint32_t*)&h;
        h = __floats2half2_rn(u0.z, u1.z); Bs2[0][bk2][bn4 + 2] = *(uint32_t*)&h;
        h = __floats2half2_rn(u0.w, u1.w); Bs2[0][bk2][bn4 + 3] = *(uint32_t*)&h;
    }
    __syncthreads();

    const int nk = K >> 4;
    for (int kt = 0; kt < nk; kt++) {
        const int cur = kt & 1, nxt = cur ^ 1;
        if (kt + 1 < nk) {
            const float* Apn = Ap + (kt + 1) * 16;
            a0 = arow_ok ? *(const float4*)Apn : make_float4(0.f, 0.f, 0.f, 0.f);
            a1 = arow_ok ? *(const float4*)(Apn + 4) : make_float4(0.f, 0.f, 0.f, 0.f);
            u0 = *(const float4*)(Bp0 + (size_t)(kt + 1) * 16 * N);
            u1 = *(const float4*)(Bp1 + (size_t)(kt + 1) * 16 * N);
        }

        uint32_t af[4][4], bf[4][2];
        #pragma unroll
        for (int mt = 0; mt < 4; mt++) {
            int r = warp_m + mt * 16 + gid;
            af[mt][0] = As2[cur][tg][r];
            af[mt][1] = As2[cur][tg][r + 8];
            af[mt][2] = As2[cur][tg + 4][r];
            af[mt][3] = As2[cur][tg + 4][r + 8];
        }
        #pragma unroll
        for (int nt = 0; nt < 4; nt++) {
            int c = warp_n + nt * 8 + gid;
            bf[nt][0] = Bs2[cur][tg][c];
            bf[nt][1] = Bs2[cur][tg + 4][c];
        }
        #pragma unroll
        for (int mt = 0; mt < 4; mt++)
            #pragma unroll
            for (int nt = 0; nt < 4; nt++) {
                asm volatile(
                    "mma.sync.aligned.m16n8k16.row.col.f32.f16.f16.f32 "
                    "{%0,%1,%2,%3}, {%4,%5,%6,%7}, {%8,%9}, {%0,%1,%2,%3};"
                    : "+f"(acc[mt][nt][0]), "+f"(acc[mt][nt][1]),
                      "+f"(acc[mt][nt][2]), "+f"(acc[mt][nt][3])
                    : "r"(af[mt][0]), "r"(af[mt][1]), "r"(af[mt][2]), "r"(af[mt][3]),
                      "r"(bf[nt][0]), "r"(bf[nt][1]));
            }

        if (kt + 1 < nk) {
            __half2 h;
            h = __floats2half2_rn(a0.x, a0.y); As2[nxt][ak2 + 0][arow] = *(uint32_t*)&h;
            h = __floats2half2_rn(a0.z, a0.w); As2[nxt][ak2 + 1][arow] = *(uint32_t*)&h;
            h = __floats2half2_rn(a1.x, a1.y); As2[nxt][ak2 + 2][arow] = *(uint32_t*)&h;
            h = __floats2half2_rn(a1.z, a1.w); As2[nxt][ak2 + 3][arow] = *(uint32_t*)&h;
            h = __floats2half2_rn(u0.x, u1.x); Bs2[nxt][bk2][bn4 + 0] = *(uint32_t*)&h;
            h = __floats2half2_rn(u0.y, u1.y); Bs2[nxt][bk2][bn4 + 1] = *(uint32_t*)&h;
            h = __floats2half2_rn(u0.z, u1.z); Bs2[nxt][bk2][bn4 + 2] = *(uint32_t*)&h;
            h = __floats2half2_rn(u0.w, u1.w); Bs2[nxt][bk2][bn4 + 3] = *(uint32_t*)&h;
        }
        __syncthreads();
    }

    #pragma unroll
    for (int mt = 0; mt < 4; mt++) {
        int r0 = bm + warp_m + mt * 16 + gid;
        #pragma unroll
        for (int nt = 0; nt < 4; nt++) {
            int c0 = bn + warp_n + nt * 8 + tg * 2;
            if (r0 < M)
                *(__half2*)&C[(size_t)r0 * N + c0] =
                    __floats2half2_rn(acc[mt][nt][0], acc[mt][nt][1]);
            if (r0 + 8 < M)
                *(__half2*)&C[(size_t)(r0 + 8) * N + c0] =
                    __floats2half2_rn(acc[mt][nt][2], acc[mt][nt][3]);
        }
    }
}

// ---------------- CSR gathers over fp16 rows ----------------
template<int LPG, int RPB, int HF_OUT>
__global__ __launch_bounds__(LPG * RPB)
void k_gather(const uint4* __restrict__ src,
              const int* __restrict__ off,
              const int* __restrict__ nbr,
              const float* __restrict__ dscale,
              const float* __restrict__ bias,
              void* __restrict__ dst, int nrows, int do_elu) {
    const int group = threadIdx.x / LPG;
    const int lane  = threadIdx.x % LPG;
    const int row = blockIdx.x * RPB + group;
    if (row >= nrows) return;
    const int s0 = off[row], s1 = off[row + 1];

    float2 acc[4] = {};
    int j = s0;
    for (; j + 1 < s1; j += 2) {
        int n0 = __ldg(&nbr[j]);
        int n1 = __ldg(&nbr[j + 1]);
        uint4 p0 = src[(size_t)n0 * LPG + lane];
        uint4 p1 = src[(size_t)n1 * LPG + lane];
        const __half2* h0 = (const __half2*)&p0;
        const __half2* h1 = (const __half2*)&p1;
        #pragma unroll
        for (int i = 0; i < 4; i++) {
            float2 f = __half22float2(__hadd2(h0[i], h1[i]));
            acc[i].x += f.x;
            acc[i].y += f.y;
        }
    }
    if (j < s1) {
        int n0 = __ldg(&nbr[j]);
        uint4 p0 = src[(size_t)n0 * LPG + lane];
        const __half2* h0 = (const __half2*)&p0;
        #pragma unroll
        for (int i = 0; i < 4; i++) {
            float2 a = __half22float2(h0[i]);
            acc[i].x += a.x;
            acc[i].y += a.y;
        }
    }
    float s = dscale[row];
    float v[8];
    #pragma unroll
    for (int i = 0; i < 4; i++) {
        v[2*i]   = acc[i].x * s;
        v[2*i+1] = acc[i].y * s;
    }
    if (HF_OUT) {
        uint4 outw;
        __half2* oh = (__half2*)&outw;
        #pragma unroll
        for (int i = 0; i < 4; i++)
            oh[i] = __floats2half2_rn(v[2*i], v[2*i+1]);
        ((uint4*)dst)[(size_t)row * LPG + lane] = outw;
    } else {
        const float* bp = bias + lane * 8;
        #pragma unroll
        for (int i = 0; i < 8; i++) v[i] += bp[i];
        if (do_elu) {
            #pragma unroll
            for (int i = 0; i < 8; i++) v[i] = v[i] > 0.f ? v[i] : expm1f(v[i]);
        }
        float4* dp = (float4*)dst + (size_t)row * (LPG * 2) + lane * 2;
        dp[0] = make_float4(v[0], v[1], v[2], v[3]);
        dp[1] = make_float4(v[4], v[5], v[6], v[7]);
    }
}

// ---------------- host driver ----------------
static inline int cdiv(int a, int b) { return (a + b - 1) / b; }

extern "C" void kernel_launch(void* const* d_in, const int* in_sizes, int n_in,
                              void* d_out, int out_size) {
    const float* x  = (const float*)d_in[0];
    const void*  ei = d_in[1];
    const float* W1 = (const float*)d_in[3];
    const float* b1 = (const float*)d_in[4];
    const float* W2 = (const float*)d_in[5];
    const float* b2 = (const float*)d_in[6];
    const float* W3 = (const float*)d_in[7];
    const float* b3 = (const float*)d_in[8];

    float *A, *B, *C, *inv_v, *inv_e;
    int *off_v, *off_e, *nbr_v, *nbr_e;
    cudaGetSymbolAddress((void**)&A, g_bufA);
    cudaGetSymbolAddress((void**)&B, g_bufB);
    cudaGetSymbolAddress((void**)&C, g_bufC);
    cudaGetSymbolAddress((void**)&inv_v, g_inv_v);
    cudaGetSymbolAddress((void**)&inv_e, g_inv_e);
    cudaGetSymbolAddress((void**)&off_v, g_off_v);
    cudaGetSymbolAddress((void**)&off_e, g_off_e);
    cudaGetSymbolAddress((void**)&nbr_v, g_nbr_v);
    cudaGetSymbolAddress((void**)&nbr_e, g_nbr_e);

    const int TB = 256;

    k_zero_all<<<cdiv(N_NODES, TB), TB>>>();
    k_detect<<<1, 32>>>((const int*)ei);
    k_convert<<<cdiv(NNZ, TB), TB>>>(ei);
    k_scanA<<<2 * NCHUNK, 256>>>();
    k_scanB<<<2, 256>>>();
    k_scanC<<<2 * NCHUNK, 256>>>();
    k_fill<<<cdiv(NNZ, TB), TB>>>();

    auto layer = [&](const float* hin, const float* W, const float* bias,
                     float* hout, int Cin, int Cout, int elu) {
        __half* msg = (__half*)A;
        __half* xe  = (__half*)B;
        dim3 gg(Cout / 128, cdiv(N_NODES, 128));
        k_hgemm<<<gg, 256>>>(hin, W, msg, N_NODES, Cin, Cout);
        if (Cout == 256) {
            k_gather<32, 8, 1><<<cdiv(N_HEDGES, 8), 256>>>(
                (const uint4*)msg, off_e, nbr_e, inv_e, nullptr,
                xe, N_HEDGES, 0);
            k_gather<32, 8, 0><<<cdiv(N_NODES, 8), 256>>>(
                (const uint4*)xe, off_v, nbr_v, inv_v, bias,
                hout, N_NODES, elu);
        } else {
            k_gather<16, 16, 1><<<cdiv(N_HEDGES, 16), 256>>>(
                (const uint4*)msg, off_e, nbr_e, inv_e, nullptr,
                xe, N_HEDGES, 0);
            k_gather<16, 16, 0><<<cdiv(N_NODES, 16), 256>>>(
                (const uint4*)xe, off_v, nbr_v, inv_v, bias,
                hout, N_NODES, elu);
        }
    };

    float* out = (float*)d_out;

    layer(x, W1, b1, C, F_IN, HID, 1);
    layer(C, W2, b2, C, HID, HID, 1);
    layer(C, W3, b3, out, HID, F_OUT, 0);
}

// round 12
// speedup vs baseline: 1.5685x; 1.0614x over previous
#include <cuda_runtime.h>
#include <cuda_fp16.h>
#include <cstdint>
#include <math.h>

#define N_NODES  50000
#define N_HEDGES 50000
#define NNZ      800000
#define F_IN     256
#define HID      256
#define F_OUT    128
#define NCHUNK   196   // ceil(50000/256)

// ---------------- scratch (device globals; no allocs allowed) ----------------
__device__ __align__(128) float g_bufA[N_NODES * HID];  // msg (fp16)
__device__ __align__(128) float g_bufB[N_NODES * HID];  // xe  (fp16)
__device__ __align__(128) float g_bufC[N_NODES * HID];  // h   (fp16)
__device__ __align__(128) float g_inv_v[N_NODES];
__device__ __align__(128) float g_inv_e[N_HEDGES];
__device__ __align__(128) int   g_cnt_v[N_NODES];
__device__ __align__(128) int   g_cnt_e[N_HEDGES];
__device__ __align__(128) int   g_cur_v[N_NODES];
__device__ __align__(128) int   g_cur_e[N_HEDGES];
__device__ __align__(128) int   g_off_v[N_NODES + 1];
__device__ __align__(128) int   g_off_e[N_HEDGES + 1];
__device__ __align__(128) int   g_vi[NNZ];
__device__ __align__(128) int   g_hi[NNZ];
__device__ __align__(128) int   g_nbr_e[NNZ];
__device__ __align__(128) int   g_nbr_v[NNZ];
__device__ __align__(128) int   g_bsum[2 * NCHUNK];
__device__ __align__(128) int   g_bbase[2 * NCHUNK];
__device__ int g_flag[1];

// ---------------- prep kernels ----------------
__global__ void k_zero_all(const int* __restrict__ ei) {
    int i = blockIdx.x * blockDim.x + threadIdx.x;
    if (i < N_NODES)  { g_cnt_v[i] = 0; g_cur_v[i] = 0; }
    if (i < N_HEDGES) { g_cnt_e[i] = 0; g_cur_e[i] = 0; }
    if (blockIdx.x == 0 && threadIdx.x == 0) {
        int z = 0;
        #pragma unroll
        for (int k = 1; k < 64; k += 2) z |= ei[k];
        g_flag[0] = (z == 0) ? 1 : 0;
    }
}

__global__ void k_convert(const void* __restrict__ ei_raw) {
    int i = blockIdx.x * blockDim.x + threadIdx.x;
    if (i >= NNZ) return;
    int v, h;
    if (g_flag[0]) {
        const long long* e = (const long long*)ei_raw;
        v = (int)e[i];
        h = (int)e[NNZ + i];
    } else {
        const int* e = (const int*)ei_raw;
        v = e[i];
        h = e[NNZ + i];
    }
    g_vi[i] = v;
    g_hi[i] = h;
    atomicAdd(&g_cnt_v[v], 1);
    atomicAdd(&g_cnt_e[h], 1);
}

__device__ __forceinline__ int block_scan_incl(int val, int* warp_sums) {
    int lane = threadIdx.x & 31, w = threadIdx.x >> 5;
    #pragma unroll
    for (int d = 1; d < 32; d <<= 1) {
        int n = __shfl_up_sync(0xffffffffu, val, d);
        if (lane >= d) val += n;
    }
    if (lane == 31) warp_sums[w] = val;
    __syncthreads();
    if (w == 0) {
        int s = (lane < 8) ? warp_sums[lane] : 0;
        #pragma unroll
        for (int d = 1; d < 8; d <<= 1) {
            int n = __shfl_up_sync(0xffffffffu, s, d);
            if (lane >= d) s += n;
        }
        if (lane < 8) warp_sums[lane] = s;
    }
    __syncthreads();
    if (w > 0) val += warp_sums[w - 1];
    return val;
}

__global__ void k_scanA() {
    __shared__ int ws[8];
    int arr = blockIdx.x / NCHUNK;
    int idx = (blockIdx.x % NCHUNK) * 256 + threadIdx.x;
    const int* cnt = arr ? g_cnt_v : g_cnt_e;
    int* off       = arr ? g_off_v : g_off_e;
    int val = (idx < 50000) ? cnt[idx] : 0;
    int incl = block_scan_incl(val, ws);
    if (idx < 50000) off[idx] = incl - val;
    if (threadIdx.x == 255) g_bsum[blockIdx.x] = incl;
}

__global__ void k_scanB() {
    __shared__ int ws[8];
    int arr = blockIdx.x;
    int i = threadIdx.x;
    int val = (i < NCHUNK) ? g_bsum[arr * NCHUNK + i] : 0;
    int incl = block_scan_incl(val, ws);
    if (i < NCHUNK) g_bbase[arr * NCHUNK + i] = incl - val;
    if (i == NCHUNK - 1) (arr ? g_off_v : g_off_e)[50000] = incl;
}

__global__ void k_scanC() {
    int arr = blockIdx.x / NCHUNK;
    int idx = (blockIdx.x % NCHUNK) * 256 + threadIdx.x;
    if (idx >= 50000) return;
    int base = g_bbase[blockIdx.x];
    if (arr) {
        g_off_v[idx] += base;
        g_inv_v[idx] = 1.0f / (float)max(g_cnt_v[idx], 1);
    } else {
        g_off_e[idx] += base;
        g_inv_e[idx] = 1.0f / (float)max(g_cnt_e[idx], 1);
    }
}

__global__ void k_fill() {
    int i = blockIdx.x * blockDim.x + threadIdx.x;
    if (i >= NNZ) return;
    int v = g_vi[i], h = g_hi[i];
    int pe = g_off_e[h] + atomicAdd(&g_cur_e[h], 1);
    g_nbr_e[pe] = v;
    int pv = g_off_v[v] + atomicAdd(&g_cur_v[v], 1);
    g_nbr_v[pv] = h;
}

// ---------------- FP16 tensor-core GEMM (fp32 accum), fp16 output -----------
// Block 128x128, k-chunk 16, 8 warps (2x4), warp tile 64x32, mma.m16n8k16.
// AHALF=0: A is fp32 (converted on load). AHALF=1: A is fp16 (direct uint4).
template<int AHALF>
__global__ __launch_bounds__(256, 2)
void k_hgemm(const void* __restrict__ Araw, const float* __restrict__ B,
             __half* __restrict__ C, int M, int K, int N) {
    __shared__ uint32_t As2[2][8][132];
    __shared__ uint32_t Bs2[2][8][132];
    const int t = threadIdx.x;
    const int lane = t & 31;
    const int warp = t >> 5;
    const int warp_m = (warp & 1) * 64;
    const int warp_n = (warp >> 1) * 32;
    const int gid = lane >> 2;
    const int tg  = lane & 3;

    const int arow = t >> 1, acol = (t & 1) * 8;
    const int ak2  = acol >> 1;            // 0 or 4
    const int bk2 = t >> 5, bn4 = (t & 31) * 4;

    const int bm = blockIdx.y * 128, bn = blockIdx.x * 128;
    const bool arow_ok = (bm + arow) < M;

    const float*  Apf = (const float*)Araw + (size_t)(bm + arow) * K + acol;
    const __half* Aph = (const __half*)Araw + (size_t)(bm + arow) * K + acol;
    const float* Bp0 = B + (size_t)(2 * bk2) * N + bn + bn4;
    const float* Bp1 = Bp0 + N;

    float acc[4][4][4] = {};
    float4 a0, a1, u0, u1;
    uint4 ah;

    // prologue load
    if (AHALF) {
        ah = arow_ok ? *(const uint4*)Aph : make_uint4(0, 0, 0, 0);
    } else {
        a0 = arow_ok ? *(const float4*)Apf : make_float4(0.f, 0.f, 0.f, 0.f);
        a1 = arow_ok ? *(const float4*)(Apf + 4) : make_float4(0.f, 0.f, 0.f, 0.f);
    }
    u0 = *(const float4*)Bp0;
    u1 = *(const float4*)Bp1;
    if (AHALF) {
        As2[0][ak2 + 0][arow] = ah.x;
        As2[0][ak2 + 1][arow] = ah.y;
        As2[0][ak2 + 2][arow] = ah.z;
        As2[0][ak2 + 3][arow] = ah.w;
    } else {
        __half2 h;
        h = __floats2half2_rn(a0.x, a0.y); As2[0][ak2 + 0][arow] = *(uint32_t*)&h;
        h = __floats2half2_rn(a0.z, a0.w); As2[0][ak2 + 1][arow] = *(uint32_t*)&h;
        h = __floats2half2_rn(a1.x, a1.y); As2[0][ak2 + 2][arow] = *(uint32_t*)&h;
        h = __floats2half2_rn(a1.z, a1.w); As2[0][ak2 + 3][arow] = *(uint32_t*)&h;
    }
    {
        __half2 h;
        h = __floats2half2_rn(u0.x, u1.x); Bs2[0][bk2][bn4 + 0] = *(uint32_t*)&h;
        h = __floats2half2_rn(u0.y, u1.y); Bs2[0][bk2][bn4 + 1] = *(uint32_t*)&h;
        h = __floats2half2_rn(u0.z, u1.z); Bs2[0][bk2][bn4 + 2] = *(uint32_t*)&h;
        h = __floats2half2_rn(u0.w, u1.w); Bs2[0][bk2][bn4 + 3] = *(uint32_t*)&h;
    }
    __syncthreads();

    const int nk = K >> 4;
    for (int kt = 0; kt < nk; kt++) {
        const int cur = kt & 1, nxt = cur ^ 1;
        if (kt + 1 < nk) {
            if (AHALF) {
                ah = arow_ok ? *(const uint4*)(Aph + (kt + 1) * 16)
                             : make_uint4(0, 0, 0, 0);
            } else {
                const float* Apn = Apf + (kt + 1) * 16;
                a0 = arow_ok ? *(const float4*)Apn : make_float4(0.f, 0.f, 0.f, 0.f);
                a1 = arow_ok ? *(const float4*)(Apn + 4) : make_float4(0.f, 0.f, 0.f, 0.f);
            }
            u0 = *(const float4*)(Bp0 + (size_t)(kt + 1) * 16 * N);
            u1 = *(const float4*)(Bp1 + (size_t)(kt + 1) * 16 * N);
        }

        uint32_t af[4][4], bf[4][2];
        #pragma unroll
        for (int mt = 0; mt < 4; mt++) {
            int r = warp_m + mt * 16 + gid;
            af[mt][0] = As2[cur][tg][r];
            af[mt][1] = As2[cur][tg][r + 8];
            af[mt][2] = As2[cur][tg + 4][r];
            af[mt][3] = As2[cur][tg + 4][r + 8];
        }
        #pragma unroll
        for (int nt = 0; nt < 4; nt++) {
            int c = warp_n + nt * 8 + gid;
            bf[nt][0] = Bs2[cur][tg][c];
            bf[nt][1] = Bs2[cur][tg + 4][c];
        }
        #pragma unroll
        for (int mt = 0; mt < 4; mt++)
            #pragma unroll
            for (int nt = 0; nt < 4; nt++) {
                asm volatile(
                    "mma.sync.aligned.m16n8k16.row.col.f32.f16.f16.f32 "
                    "{%0,%1,%2,%3}, {%4,%5,%6,%7}, {%8,%9}, {%0,%1,%2,%3};"
                    : "+f"(acc[mt][nt][0]), "+f"(acc[mt][nt][1]),
                      "+f"(acc[mt][nt][2]), "+f"(acc[mt][nt][3])
                    : "r"(af[mt][0]), "r"(af[mt][1]), "r"(af[mt][2]), "r"(af[mt][3]),
                      "r"(bf[nt][0]), "r"(bf[nt][1]));
            }

        if (kt + 1 < nk) {
            if (AHALF) {
                As2[nxt][ak2 + 0][arow] = ah.x;
                As2[nxt][ak2 + 1][arow] = ah.y;
                As2[nxt][ak2 + 2][arow] = ah.z;
                As2[nxt][ak2 + 3][arow] = ah.w;
            } else {
                __half2 h;
                h = __floats2half2_rn(a0.x, a0.y); As2[nxt][ak2 + 0][arow] = *(uint32_t*)&h;
                h = __floats2half2_rn(a0.z, a0.w); As2[nxt][ak2 + 1][arow] = *(uint32_t*)&h;
                h = __floats2half2_rn(a1.x, a1.y); As2[nxt][ak2 + 2][arow] = *(uint32_t*)&h;
                h = __floats2half2_rn(a1.z, a1.w); As2[nxt][ak2 + 3][arow] = *(uint32_t*)&h;
            }
            __half2 h;
            h = __floats2half2_rn(u0.x, u1.x); Bs2[nxt][bk2][bn4 + 0] = *(uint32_t*)&h;
            h = __floats2half2_rn(u0.y, u1.y); Bs2[nxt][bk2][bn4 + 1] = *(uint32_t*)&h;
            h = __floats2half2_rn(u0.z, u1.z); Bs2[nxt][bk2][bn4 + 2] = *(uint32_t*)&h;
            h = __floats2half2_rn(u0.w, u1.w); Bs2[nxt][bk2][bn4 + 3] = *(uint32_t*)&h;
        }
        __syncthreads();
    }

    #pragma unroll
    for (int mt = 0; mt < 4; mt++) {
        int r0 = bm + warp_m + mt * 16 + gid;
        #pragma unroll
        for (int nt = 0; nt < 4; nt++) {
            int c0 = bn + warp_n + nt * 8 + tg * 2;
            if (r0 < M)
                *(__half2*)&C[(size_t)r0 * N + c0] =
                    __floats2half2_rn(acc[mt][nt][0], acc[mt][nt][1]);
            if (r0 + 8 < M)
                *(__half2*)&C[(size_t)(r0 + 8) * N + c0] =
                    __floats2half2_rn(acc[mt][nt][2], acc[mt][nt][3]);
        }
    }
}

// ---------------- CSR gathers over fp16 rows ----------------
// OUT_MODE: 0 = fp16, no bias (v->e).  1 = fp16 + bias + ELU (e->v, layers 1-2)
//           2 = fp32 + bias, no ELU (e->v, final layer)
template<int LPG, int RPB, int OUT_MODE>
__global__ __launch_bounds__(LPG * RPB)
void k_gather(const uint4* __restrict__ src,
              const int* __restrict__ off,
              const int* __restrict__ nbr,
              const float* __restrict__ dscale,
              const float* __restrict__ bias,
              void* __restrict__ dst, int nrows) {
    const int group = threadIdx.x / LPG;
    const int lane  = threadIdx.x % LPG;
    const int row = blockIdx.x * RPB + group;
    if (row >= nrows) return;
    const int s0 = off[row], s1 = off[row + 1];

    float2 acc[4] = {};
    int j = s0;
    for (; j + 1 < s1; j += 2) {
        int n0 = __ldg(&nbr[j]);
        int n1 = __ldg(&nbr[j + 1]);
        uint4 p0 = src[(size_t)n0 * LPG + lane];
        uint4 p1 = src[(size_t)n1 * LPG + lane];
        const __half2* h0 = (const __half2*)&p0;
        const __half2* h1 = (const __half2*)&p1;
        #pragma unroll
        for (int i = 0; i < 4; i++) {
            float2 f = __half22float2(__hadd2(h0[i], h1[i]));
            acc[i].x += f.x;
            acc[i].y += f.y;
        }
    }
    if (j < s1) {
        int n0 = __ldg(&nbr[j]);
        uint4 p0 = src[(size_t)n0 * LPG + lane];
        const __half2* h0 = (const __half2*)&p0;
        #pragma unroll
        for (int i = 0; i < 4; i++) {
            float2 a = __half22float2(h0[i]);
            acc[i].x += a.x;
            acc[i].y += a.y;
        }
    }
    float s = dscale[row];
    float v[8];
    #pragma unroll
    for (int i = 0; i < 4; i++) {
        v[2*i]   = acc[i].x * s;
        v[2*i+1] = acc[i].y * s;
    }
    if (OUT_MODE == 0) {
        uint4 outw;
        __half2* oh = (__half2*)&outw;
        #pragma unroll
        for (int i = 0; i < 4; i++)
            oh[i] = __floats2half2_rn(v[2*i], v[2*i+1]);
        ((uint4*)dst)[(size_t)row * LPG + lane] = outw;
    } else {
        const float* bp = bias + lane * 8;
        #pragma unroll
        for (int i = 0; i < 8; i++) v[i] += bp[i];
        if (OUT_MODE == 1) {
            #pragma unroll
            for (int i = 0; i < 8; i++) v[i] = v[i] > 0.f ? v[i] : expm1f(v[i]);
            uint4 outw;
            __half2* oh = (__half2*)&outw;
            #pragma unroll
            for (int i = 0; i < 4; i++)
                oh[i] = __floats2half2_rn(v[2*i], v[2*i+1]);
            ((uint4*)dst)[(size_t)row * LPG + lane] = outw;
        } else {
            float4* dp = (float4*)dst + (size_t)row * (LPG * 2) + lane * 2;
            dp[0] = make_float4(v[0], v[1], v[2], v[3]);
            dp[1] = make_float4(v[4], v[5], v[6], v[7]);
        }
    }
}

// ---------------- host driver ----------------
static inline int cdiv(int a, int b) { return (a + b - 1) / b; }

extern "C" void kernel_launch(void* const* d_in, const int* in_sizes, int n_in,
                              void* d_out, int out_size) {
    const float* x  = (const float*)d_in[0];
    const void*  ei = d_in[1];
    const float* W1 = (const float*)d_in[3];
    const float* b1 = (const float*)d_in[4];
    const float* W2 = (const float*)d_in[5];
    const float* b2 = (const float*)d_in[6];
    const float* W3 = (const float*)d_in[7];
    const float* b3 = (const float*)d_in[8];

    float *A, *B, *C, *inv_v, *inv_e;
    int *off_v, *off_e, *nbr_v, *nbr_e;
    cudaGetSymbolAddress((void**)&A, g_bufA);
    cudaGetSymbolAddress((void**)&B, g_bufB);
    cudaGetSymbolAddress((void**)&C, g_bufC);
    cudaGetSymbolAddress((void**)&inv_v, g_inv_v);
    cudaGetSymbolAddress((void**)&inv_e, g_inv_e);
    cudaGetSymbolAddress((void**)&off_v, g_off_v);
    cudaGetSymbolAddress((void**)&off_e, g_off_e);
    cudaGetSymbolAddress((void**)&nbr_v, g_nbr_v);
    cudaGetSymbolAddress((void**)&nbr_e, g_nbr_e);

    const int TB = 256;

    k_zero_all<<<cdiv(N_NODES, TB), TB>>>((const int*)ei);
    k_convert<<<cdiv(NNZ, TB), TB>>>(ei);
    k_scanA<<<2 * NCHUNK, 256>>>();
    k_scanB<<<2, 256>>>();
    k_scanC<<<2 * NCHUNK, 256>>>();
    k_fill<<<cdiv(NNZ, TB), TB>>>();

    __half* msg = (__half*)A;
    __half* xe  = (__half*)B;
    __half* h   = (__half*)C;
    float*  out = (float*)d_out;

    // Layer 1: x (fp32) -> msg -> xe -> h (fp16, bias+ELU)
    {
        dim3 gg(HID / 128, cdiv(N_NODES, 128));
        k_hgemm<0><<<gg, 256>>>(x, W1, msg, N_NODES, F_IN, HID);
        k_gather<32, 8, 0><<<cdiv(N_HEDGES, 8), 256>>>(
            (const uint4*)msg, off_e, nbr_e, inv_e, nullptr, xe, N_HEDGES);
        k_gather<32, 8, 1><<<cdiv(N_NODES, 8), 256>>>(
            (const uint4*)xe, off_v, nbr_v, inv_v, b1, h, N_NODES);
    }
    // Layer 2: h (fp16) -> msg -> xe -> h (fp16, bias+ELU)
    {
        dim3 gg(HID / 128, cdiv(N_NODES, 128));
        k_hgemm<1><<<gg, 256>>>(h, W2, msg, N_NODES, HID, HID);
        k_gather<32, 8, 0><<<cdiv(N_HEDGES, 8), 256>>>(
            (const uint4*)msg, off_e, nbr_e, inv_e, nullptr, xe, N_HEDGES);
        k_gather<32, 8, 1><<<cdiv(N_NODES, 8), 256>>>(
            (const uint4*)xe, off_v, nbr_v, inv_v, b2, h, N_NODES);
    }
    // Layer 3: h (fp16) -> msg -> xe -> out (fp32, bias, no ELU)
    {
        dim3 gg(F_OUT / 128, cdiv(N_NODES, 128));
        k_hgemm<1><<<gg, 256>>>(h, W3, msg, N_NODES, HID, F_OUT);
        k_gather<16, 16, 0><<<cdiv(N_HEDGES, 16), 256>>>(
            (const uint4*)msg, off_e, nbr_e, inv_e, nullptr, xe, N_HEDGES);
        k_gather<16, 16, 2><<<cdiv(N_NODES, 16), 256>>>(
            (const uint4*)xe, off_v, nbr_v, inv_v, b3, out, N_NODES);
    }
}

// round 13
// speedup vs baseline: 1.6563x; 1.0560x over previous
#include <cuda_runtime.h>
#include <cuda_fp16.h>
#include <cstdint>
#include <math.h>

#define N_NODES  50000
#define N_HEDGES 50000
#define NNZ      800000
#define F_IN     256
#define HID      256
#define F_OUT    128
#define NCHUNK   196   // ceil(50000/256)

// Packed W offsets (uint32 = half2 units, k-paired layout [K/2][N])
#define WP1_OFF  0
#define WP2_OFF  32768          // 128*256
#define WP3_OFF  65536          // + 128*256
#define WP_TOTAL 81920          // + 128*128

// ---------------- scratch (device globals; no allocs allowed) ----------------
__device__ __align__(128) float g_bufA[N_NODES * HID];  // msg (fp16)
__device__ __align__(128) float g_bufB[N_NODES * HID];  // xh / xe (fp16)
__device__ __align__(128) float g_bufC[N_NODES * HID];  // h   (fp16)
__device__ __align__(128) uint32_t g_Wp[WP_TOTAL];      // packed fp16 weights
__device__ __align__(128) float g_inv_v[N_NODES];
__device__ __align__(128) float g_inv_e[N_HEDGES];
__device__ __align__(128) int   g_cnt_v[N_NODES];
__device__ __align__(128) int   g_cnt_e[N_HEDGES];
__device__ __align__(128) int   g_cur_v[N_NODES];
__device__ __align__(128) int   g_cur_e[N_HEDGES];
__device__ __align__(128) int   g_off_v[N_NODES + 1];
__device__ __align__(128) int   g_off_e[N_HEDGES + 1];
__device__ __align__(128) int   g_vi[NNZ];
__device__ __align__(128) int   g_hi[NNZ];
__device__ __align__(128) int   g_nbr_e[NNZ];
__device__ __align__(128) int   g_nbr_v[NNZ];
__device__ __align__(128) int   g_bsum[2 * NCHUNK];
__device__ __align__(128) int   g_bbase[2 * NCHUNK];
__device__ int g_flag[1];

// ---------------- prep kernels ----------------
__global__ void k_zero_all(const int* __restrict__ ei) {
    int i = blockIdx.x * blockDim.x + threadIdx.x;
    if (i < N_NODES)  { g_cnt_v[i] = 0; g_cur_v[i] = 0; }
    if (i < N_HEDGES) { g_cnt_e[i] = 0; g_cur_e[i] = 0; }
    if (blockIdx.x == 0 && threadIdx.x == 0) {
        int z = 0;
        #pragma unroll
        for (int k = 1; k < 64; k += 2) z |= ei[k];
        g_flag[0] = (z == 0) ? 1 : 0;
    }
}

__global__ void k_convert(const void* __restrict__ ei_raw) {
    int i = blockIdx.x * blockDim.x + threadIdx.x;
    if (i >= NNZ) return;
    int v, h;
    if (g_flag[0]) {
        const long long* e = (const long long*)ei_raw;
        v = (int)e[i];
        h = (int)e[NNZ + i];
    } else {
        const int* e = (const int*)ei_raw;
        v = e[i];
        h = e[NNZ + i];
    }
    g_vi[i] = v;
    g_hi[i] = h;
    atomicAdd(&g_cnt_v[v], 1);
    atomicAdd(&g_cnt_e[h], 1);
}

__device__ __forceinline__ int block_scan_incl(int val, int* warp_sums) {
    int lane = threadIdx.x & 31, w = threadIdx.x >> 5;
    #pragma unroll
    for (int d = 1; d < 32; d <<= 1) {
        int n = __shfl_up_sync(0xffffffffu, val, d);
        if (lane >= d) val += n;
    }
    if (lane == 31) warp_sums[w] = val;
    __syncthreads();
    if (w == 0) {
        int s = (lane < 8) ? warp_sums[lane] : 0;
        #pragma unroll
        for (int d = 1; d < 8; d <<= 1) {
            int n = __shfl_up_sync(0xffffffffu, s, d);
            if (lane >= d) s += n;
        }
        if (lane < 8) warp_sums[lane] = s;
    }
    __syncthreads();
    if (w > 0) val += warp_sums[w - 1];
    return val;
}

__global__ void k_scanA() {
    __shared__ int ws[8];
    int arr = blockIdx.x / NCHUNK;
    int idx = (blockIdx.x % NCHUNK) * 256 + threadIdx.x;
    const int* cnt = arr ? g_cnt_v : g_cnt_e;
    int* off       = arr ? g_off_v : g_off_e;
    int val = (idx < 50000) ? cnt[idx] : 0;
    int incl = block_scan_incl(val, ws);
    if (idx < 50000) off[idx] = incl - val;
    if (threadIdx.x == 255) g_bsum[blockIdx.x] = incl;
}

__global__ void k_scanB() {
    __shared__ int ws[8];
    int arr = blockIdx.x;
    int i = threadIdx.x;
    int val = (i < NCHUNK) ? g_bsum[arr * NCHUNK + i] : 0;
    int incl = block_scan_incl(val, ws);
    if (i < NCHUNK) g_bbase[arr * NCHUNK + i] = incl - val;
    if (i == NCHUNK - 1) (arr ? g_off_v : g_off_e)[50000] = incl;
}

__global__ void k_scanC() {
    int arr = blockIdx.x / NCHUNK;
    int idx = (blockIdx.x % NCHUNK) * 256 + threadIdx.x;
    if (idx >= 50000) return;
    int base = g_bbase[blockIdx.x];
    if (arr) {
        g_off_v[idx] += base;
        g_inv_v[idx] = 1.0f / (float)max(g_cnt_v[idx], 1);
    } else {
        g_off_e[idx] += base;
        g_inv_e[idx] = 1.0f / (float)max(g_cnt_e[idx], 1);
    }
}

__global__ void k_fill() {
    int i = blockIdx.x * blockDim.x + threadIdx.x;
    if (i >= NNZ) return;
    int v = g_vi[i], h = g_hi[i];
    int pe = g_off_e[h] + atomicAdd(&g_cur_e[h], 1);
    g_nbr_e[pe] = v;
    int pv = g_off_v[v] + atomicAdd(&g_cur_v[v], 1);
    g_nbr_v[pv] = h;
}

// ---------------- packing kernels ----------------
// Pack W (fp32 [K][N] row-major) into k-paired half2: Wp[k2*N + n] = (W[2k2][n], W[2k2+1][n])
__global__ void k_packW(const float* __restrict__ W1, const float* __restrict__ W2,
                        const float* __restrict__ W3) {
    int i = blockIdx.x * blockDim.x + threadIdx.x;
    if (i >= WP_TOTAL) return;
    const float* W; int base, N;
    if (i < WP2_OFF)      { W = W1; base = i;           N = HID;  }
    else if (i < WP3_OFF) { W = W2; base = i - WP2_OFF; N = HID;  }
    else                  { W = W3; base = i - WP3_OFF; N = F_OUT; }
    int k2 = base / N, n = base % N;
    __half2 h = __floats2half2_rn(W[(2 * k2) * N + n], W[(2 * k2 + 1) * N + n]);
    g_Wp[i] = *(uint32_t*)&h;
}

// Pack x (fp32) into fp16. 8 elems per thread.
__global__ void k_packX(const float* __restrict__ x, __half* __restrict__ xh) {
    int i = blockIdx.x * blockDim.x + threadIdx.x;
    if (i >= N_NODES * F_IN / 8) return;
    const float4* p = (const float4*)(x + (size_t)i * 8);
    float4 a = p[0], b = p[1];
    uint4 o;
    __half2 h;
    h = __floats2half2_rn(a.x, a.y); o.x = *(uint32_t*)&h;
    h = __floats2half2_rn(a.z, a.w); o.y = *(uint32_t*)&h;
    h = __floats2half2_rn(b.x, b.y); o.z = *(uint32_t*)&h;
    h = __floats2half2_rn(b.z, b.w); o.w = *(uint32_t*)&h;
    ((uint4*)xh)[i] = o;
}

// ---------------- FP16 tensor-core GEMM (fp32 accum), fp16 out --------------
// A: fp16 row-major [M][K]. Bp: pre-packed half2 [K/2][N]. mma.m16n8k16.
__global__ __launch_bounds__(256, 2)
void k_hgemm(const __half* __restrict__ A, const uint32_t* __restrict__ Bp,
             __half* __restrict__ C, int M, int K, int N) {
    __shared__ uint32_t As2[2][8][132];
    __shared__ uint32_t Bs2[2][8][132];
    const int t = threadIdx.x;
    const int lane = t & 31;
    const int warp = t >> 5;
    const int warp_m = (warp & 1) * 64;
    const int warp_n = (warp >> 1) * 32;
    const int gid = lane >> 2;
    const int tg  = lane & 3;

    const int arow = t >> 1, ak2 = (t & 1) * 4;     // 8 halves per thread
    const int bk2 = t >> 5,  bn4 = (t & 31) * 4;    // 4 half2 per thread

    const int bm = blockIdx.y * 128, bn = blockIdx.x * 128;
    const bool arow_ok = (bm + arow) < M;
    const __half* Ap = A + (size_t)(bm + arow) * K + ak2 * 2;
    const uint32_t* Bpp = Bp + (size_t)bk2 * N + bn + bn4;

    float acc[4][4][4] = {};
    uint4 ah, bw;

    ah = arow_ok ? *(const uint4*)Ap : make_uint4(0, 0, 0, 0);
    bw = *(const uint4*)Bpp;
    As2[0][ak2 + 0][arow] = ah.x;
    As2[0][ak2 + 1][arow] = ah.y;
    As2[0][ak2 + 2][arow] = ah.z;
    As2[0][ak2 + 3][arow] = ah.w;
    Bs2[0][bk2][bn4 + 0] = bw.x;
    Bs2[0][bk2][bn4 + 1] = bw.y;
    Bs2[0][bk2][bn4 + 2] = bw.z;
    Bs2[0][bk2][bn4 + 3] = bw.w;
    __syncthreads();

    const int nk = K >> 4;
    for (int kt = 0; kt < nk; kt++) {
        const int cur = kt & 1, nxt = cur ^ 1;
        if (kt + 1 < nk) {
            ah = arow_ok ? *(const uint4*)(Ap + (kt + 1) * 16) : make_uint4(0, 0, 0, 0);
            bw = *(const uint4*)(Bpp + (size_t)(kt + 1) * 8 * N);
        }

        uint32_t af[4][4], bf[4][2];
        #pragma unroll
        for (int mt = 0; mt < 4; mt++) {
            int r = warp_m + mt * 16 + gid;
            af[mt][0] = As2[cur][tg][r];
            af[mt][1] = As2[cur][tg][r + 8];
            af[mt][2] = As2[cur][tg + 4][r];
            af[mt][3] = As2[cur][tg + 4][r + 8];
        }
        #pragma unroll
        for (int nt = 0; nt < 4; nt++) {
            int c = warp_n + nt * 8 + gid;
            bf[nt][0] = Bs2[cur][tg][c];
            bf[nt][1] = Bs2[cur][tg + 4][c];
        }
        #pragma unroll
        for (int mt = 0; mt < 4; mt++)
            #pragma unroll
            for (int nt = 0; nt < 4; nt++) {
                asm volatile(
                    "mma.sync.aligned.m16n8k16.row.col.f32.f16.f16.f32 "
                    "{%0,%1,%2,%3}, {%4,%5,%6,%7}, {%8,%9}, {%0,%1,%2,%3};"
                    : "+f"(acc[mt][nt][0]), "+f"(acc[mt][nt][1]),
                      "+f"(acc[mt][nt][2]), "+f"(acc[mt][nt][3])
                    : "r"(af[mt][0]), "r"(af[mt][1]), "r"(af[mt][2]), "r"(af[mt][3]),
                      "r"(bf[nt][0]), "r"(bf[nt][1]));
            }

        if (kt + 1 < nk) {
            As2[nxt][ak2 + 0][arow] = ah.x;
            As2[nxt][ak2 + 1][arow] = ah.y;
            As2[nxt][ak2 + 2][arow] = ah.z;
            As2[nxt][ak2 + 3][arow] = ah.w;
            Bs2[nxt][bk2][bn4 + 0] = bw.x;
            Bs2[nxt][bk2][bn4 + 1] = bw.y;
            Bs2[nxt][bk2][bn4 + 2] = bw.z;
            Bs2[nxt][bk2][bn4 + 3] = bw.w;
        }
        __syncthreads();
    }

    #pragma unroll
    for (int mt = 0; mt < 4; mt++) {
        int r0 = bm + warp_m + mt * 16 + gid;
        #pragma unroll
        for (int nt = 0; nt < 4; nt++) {
            int c0 = bn + warp_n + nt * 8 + tg * 2;
            if (r0 < M)
                *(__half2*)&C[(size_t)r0 * N + c0] =
                    __floats2half2_rn(acc[mt][nt][0], acc[mt][nt][1]);
            if (r0 + 8 < M)
                *(__half2*)&C[(size_t)(r0 + 8) * N + c0] =
                    __floats2half2_rn(acc[mt][nt][2], acc[mt][nt][3]);
        }
    }
}

// ---------------- CSR gathers over fp16 rows ----------------
// OUT_MODE: 0 = fp16, no bias (v->e). 1 = fp16 + bias + ELU. 2 = fp32 + bias.
template<int LPG, int RPB, int OUT_MODE>
__global__ __launch_bounds__(LPG * RPB)
void k_gather(const uint4* __restrict__ src,
              const int* __restrict__ off,
              const int* __restrict__ nbr,
              const float* __restrict__ dscale,
              const float* __restrict__ bias,
              void* __restrict__ dst, int nrows) {
    const int group = threadIdx.x / LPG;
    const int lane  = threadIdx.x % LPG;
    const int row = blockIdx.x * RPB + group;
    if (row >= nrows) return;
    const int s0 = off[row], s1 = off[row + 1];

    float2 acc[4] = {};
    int j = s0;
    for (; j + 1 < s1; j += 2) {
        int n0 = __ldg(&nbr[j]);
        int n1 = __ldg(&nbr[j + 1]);
        uint4 p0 = src[(size_t)n0 * LPG + lane];
        uint4 p1 = src[(size_t)n1 * LPG + lane];
        const __half2* h0 = (const __half2*)&p0;
        const __half2* h1 = (const __half2*)&p1;
        #pragma unroll
        for (int i = 0; i < 4; i++) {
            float2 f = __half22float2(__hadd2(h0[i], h1[i]));
            acc[i].x += f.x;
            acc[i].y += f.y;
        }
    }
    if (j < s1) {
        int n0 = __ldg(&nbr[j]);
        uint4 p0 = src[(size_t)n0 * LPG + lane];
        const __half2* h0 = (const __half2*)&p0;
        #pragma unroll
        for (int i = 0; i < 4; i++) {
            float2 a = __half22float2(h0[i]);
            acc[i].x += a.x;
            acc[i].y += a.y;
        }
    }
    float s = dscale[row];
    float v[8];
    #pragma unroll
    for (int i = 0; i < 4; i++) {
        v[2*i]   = acc[i].x * s;
        v[2*i+1] = acc[i].y * s;
    }
    if (OUT_MODE == 0) {
        uint4 outw;
        __half2* oh = (__half2*)&outw;
        #pragma unroll
        for (int i = 0; i < 4; i++)
            oh[i] = __floats2half2_rn(v[2*i], v[2*i+1]);
        ((uint4*)dst)[(size_t)row * LPG + lane] = outw;
    } else {
        const float* bp = bias + lane * 8;
        #pragma unroll
        for (int i = 0; i < 8; i++) v[i] += bp[i];
        if (OUT_MODE == 1) {
            #pragma unroll
            for (int i = 0; i < 8; i++) v[i] = v[i] > 0.f ? v[i] : expm1f(v[i]);
            uint4 outw;
            __half2* oh = (__half2*)&outw;
            #pragma unroll
            for (int i = 0; i < 4; i++)
                oh[i] = __floats2half2_rn(v[2*i], v[2*i+1]);
            ((uint4*)dst)[(size_t)row * LPG + lane] = outw;
        } else {
            float4* dp = (float4*)dst + (size_t)row * (LPG * 2) + lane * 2;
            dp[0] = make_float4(v[0], v[1], v[2], v[3]);
            dp[1] = make_float4(v[4], v[5], v[6], v[7]);
        }
    }
}

// ---------------- host driver ----------------
static inline int cdiv(int a, int b) { return (a + b - 1) / b; }

extern "C" void kernel_launch(void* const* d_in, const int* in_sizes, int n_in,
                              void* d_out, int out_size) {
    const float* x  = (const float*)d_in[0];
    const void*  ei = d_in[1];
    const float* W1 = (const float*)d_in[3];
    const float* b1 = (const float*)d_in[4];
    const float* W2 = (const float*)d_in[5];
    const float* b2 = (const float*)d_in[6];
    const float* W3 = (const float*)d_in[7];
    const float* b3 = (const float*)d_in[8];

    float *A, *B, *C, *inv_v, *inv_e;
    uint32_t* Wp;
    int *off_v, *off_e, *nbr_v, *nbr_e;
    cudaGetSymbolAddress((void**)&A, g_bufA);
    cudaGetSymbolAddress((void**)&B, g_bufB);
    cudaGetSymbolAddress((void**)&C, g_bufC);
    cudaGetSymbolAddress((void**)&Wp, g_Wp);
    cudaGetSymbolAddress((void**)&inv_v, g_inv_v);
    cudaGetSymbolAddress((void**)&inv_e, g_inv_e);
    cudaGetSymbolAddress((void**)&off_v, g_off_v);
    cudaGetSymbolAddress((void**)&off_e, g_off_e);
    cudaGetSymbolAddress((void**)&nbr_v, g_nbr_v);
    cudaGetSymbolAddress((void**)&nbr_e, g_nbr_e);

    const int TB = 256;

    __half* msg = (__half*)A;
    __half* xh  = (__half*)B;   // layer-1 A operand, later reused as xe
    __half* xe  = (__half*)B;
    __half* h   = (__half*)C;
    float*  out = (float*)d_out;

    // Fork: side stream does {packW, packX, GEMM1} while stream 0 does CSR prep.
    cudaStream_t s2;
    cudaStreamCreateWithFlags(&s2, cudaStreamNonBlocking);
    cudaEvent_t evFork, evJoin;
    cudaEventCreateWithFlags(&evFork, cudaEventDisableTiming);
    cudaEventCreateWithFlags(&evJoin, cudaEventDisableTiming);

    cudaEventRecord(evFork, 0);
    cudaStreamWaitEvent(s2, evFork, 0);

    // ---- side stream: weight/x packing + layer-1 GEMM ----
    k_packW<<<cdiv(WP_TOTAL, TB), TB, 0, s2>>>(W1, W2, W3);
    k_packX<<<cdiv(N_NODES * F_IN / 8, TB), TB, 0, s2>>>(x, xh);
    {
        dim3 gg(HID / 128, cdiv(N_NODES, 128));
        k_hgemm<<<gg, 256, 0, s2>>>(xh, Wp + WP1_OFF, msg, N_NODES, F_IN, HID);
    }
    cudaEventRecord(evJoin, s2);

    // ---- stream 0: CSR prep ----
    k_zero_all<<<cdiv(N_NODES, TB), TB>>>((const int*)ei);
    k_convert<<<cdiv(NNZ, TB), TB>>>(ei);
    k_scanA<<<2 * NCHUNK, 256>>>();
    k_scanB<<<2, 256>>>();
    k_scanC<<<2 * NCHUNK, 256>>>();
    k_fill<<<cdiv(NNZ, TB), TB>>>();

    cudaStreamWaitEvent(0, evJoin, 0);

    // ---- layer 1 gathers ----
    k_gather<32, 8, 0><<<cdiv(N_HEDGES, 8), 256>>>(
        (const uint4*)msg, off_e, nbr_e, inv_e, nullptr, xe, N_HEDGES);
    k_gather<32, 8, 1><<<cdiv(N_NODES, 8), 256>>>(
        (const uint4*)xe, off_v, nbr_v, inv_v, b1, h, N_NODES);

    // ---- layer 2 ----
    {
        dim3 gg(HID / 128, cdiv(N_NODES, 128));
        k_hgemm<<<gg, 256>>>(h, Wp + WP2_OFF, msg, N_NODES, HID, HID);
        k_gather<32, 8, 0><<<cdiv(N_HEDGES, 8), 256>>>(
            (const uint4*)msg, off_e, nbr_e, inv_e, nullptr, xe, N_HEDGES);
        k_gather<32, 8, 1><<<cdiv(N_NODES, 8), 256>>>(
            (const uint4*)xe, off_v, nbr_v, inv_v, b2, h, N_NODES);
    }
    // ---- layer 3 ----
    {
        dim3 gg(F_OUT / 128, cdiv(N_NODES, 128));
        k_hgemm<<<gg, 256>>>(h, Wp + WP3_OFF, msg, N_NODES, HID, F_OUT);
        k_gather<16, 16, 0><<<cdiv(N_HEDGES, 16), 256>>>(
            (const uint4*)msg, off_e, nbr_e, inv_e, nullptr, xe, N_HEDGES);
        k_gather<16, 16, 2><<<cdiv(N_NODES, 16), 256>>>(
            (const uint4*)xe, off_v, nbr_v, inv_v, b3, out, N_NODES);
    }
}

// round 15
// speedup vs baseline: 1.6620x; 1.0034x over previous
#include <cuda_runtime.h>
#include <cuda_fp16.h>
#include <cstdint>
#include <math.h>

#define N_NODES  50000
#define N_HEDGES 50000
#define NNZ      800000
#define F_IN     256
#define HID      256
#define F_OUT    128
#define NCHUNK   196   // ceil(50000/256)

// Packed W offsets (uint32 = half2 units, k-paired layout [K/2][N])
#define WP1_OFF  0
#define WP2_OFF  32768          // 128*256
#define WP3_OFF  65536          // + 128*256
#define WP_TOTAL 81920          // + 128*128

// ---------------- scratch (device globals; no allocs allowed) ----------------
__device__ __align__(128) float g_bufA[N_NODES * HID];  // msg (fp16)
__device__ __align__(128) float g_bufB[N_NODES * HID];  // xh / xe (fp16)
__device__ __align__(128) float g_bufC[N_NODES * HID];  // h   (fp16)
__device__ __align__(128) uint32_t g_Wp[WP_TOTAL];      // packed fp16 weights
__device__ __align__(128) float g_inv_v[N_NODES];
__device__ __align__(128) float g_inv_e[N_HEDGES];
__device__ __align__(128) int   g_cnt_v[N_NODES];
__device__ __align__(128) int   g_cnt_e[N_HEDGES];
__device__ __align__(128) int   g_cur_v[N_NODES];
__device__ __align__(128) int   g_cur_e[N_HEDGES];
__device__ __align__(128) int   g_off_v[N_NODES + 1];
__device__ __align__(128) int   g_off_e[N_HEDGES + 1];
__device__ __align__(128) int   g_vi[NNZ];
__device__ __align__(128) int   g_hi[NNZ];
__device__ __align__(128) int   g_nbr_e[NNZ];
__device__ __align__(128) int   g_nbr_v[NNZ];
__device__ __align__(128) int   g_bsum[2 * NCHUNK];
__device__ int g_flag[1];

// ---------------- prep kernels ----------------
__global__ void k_zero_all(const int* __restrict__ ei) {
    int i = blockIdx.x * blockDim.x + threadIdx.x;
    if (i < N_NODES)  { g_cnt_v[i] = 0; g_cur_v[i] = 0; }
    if (i < N_HEDGES) { g_cnt_e[i] = 0; g_cur_e[i] = 0; }
    if (blockIdx.x == 0 && threadIdx.x == 0) {
        int z = 0;
        #pragma unroll
        for (int k = 1; k < 64; k += 2) z |= ei[k];
        g_flag[0] = (z == 0) ? 1 : 0;
    }
}

__global__ void k_convert(const void* __restrict__ ei_raw) {
    int i = blockIdx.x * blockDim.x + threadIdx.x;
    if (i >= NNZ) return;
    int v, h;
    if (g_flag[0]) {
        const long long* e = (const long long*)ei_raw;
        v = (int)e[i];
        h = (int)e[NNZ + i];
    } else {
        const int* e = (const int*)ei_raw;
        v = e[i];
        h = e[NNZ + i];
    }
    g_vi[i] = v;
    g_hi[i] = h;
    atomicAdd(&g_cnt_v[v], 1);
    atomicAdd(&g_cnt_e[h], 1);
}

__device__ __forceinline__ int block_scan_incl(int val, int* warp_sums) {
    int lane = threadIdx.x & 31, w = threadIdx.x >> 5;
    #pragma unroll
    for (int d = 1; d < 32; d <<= 1) {
        int n = __shfl_up_sync(0xffffffffu, val, d);
        if (lane >= d) val += n;
    }
    if (lane == 31) warp_sums[w] = val;
    __syncthreads();
    if (w == 0) {
        int s = (lane < 8) ? warp_sums[lane] : 0;
        #pragma unroll
        for (int d = 1; d < 8; d <<= 1) {
            int n = __shfl_up_sync(0xffffffffu, s, d);
            if (lane >= d) s += n;
        }
        if (lane < 8) warp_sums[lane] = s;
    }
    __syncthreads();
    if (w > 0) val += warp_sums[w - 1];
    return val;
}

// Phase A (per array): block-local exclusive scans + block sums. arr: 0=e, 1=v.
__global__ void k_scanA(int arr) {
    __shared__ int ws[8];
    int idx = blockIdx.x * 256 + threadIdx.x;
    const int* cnt = arr ? g_cnt_v : g_cnt_e;
    int* off       = arr ? g_off_v : g_off_e;
    int val = (idx < 50000) ? cnt[idx] : 0;
    int incl = block_scan_incl(val, ws);
    if (idx < 50000) off[idx] = incl - val;
    if (threadIdx.x == 255) g_bsum[arr * NCHUNK + blockIdx.x] = incl;
}

// Phase C (per array): block base via warp-reduce over earlier block sums;
// adds base, computes inverse degree. off[50000] = NNZ.
__global__ void k_scanC(int arr) {
    __shared__ int sbase;
    int blk = blockIdx.x;
    int idx = blk * 256 + threadIdx.x;
    if (threadIdx.x < 32) {
        int s = 0;
        for (int i = threadIdx.x; i < blk; i += 32) s += g_bsum[arr * NCHUNK + i];
        #pragma unroll
        for (int d = 16; d; d >>= 1) s += __shfl_down_sync(0xffffffffu, s, d);
        if (threadIdx.x == 0) sbase = s;
    }
    __syncthreads();
    int base = sbase;
    if (idx < 50000) {
        if (arr) {
            g_off_v[idx] += base;
            g_inv_v[idx] = 1.0f / (float)max(g_cnt_v[idx], 1);
        } else {
            g_off_e[idx] += base;
            g_inv_e[idx] = 1.0f / (float)max(g_cnt_e[idx], 1);
        }
    }
    if (idx == 49999) (arr ? g_off_v : g_off_e)[50000] = NNZ;
}

__global__ void k_fill_e() {
    int i = blockIdx.x * blockDim.x + threadIdx.x;
    if (i >= NNZ) return;
    int v = g_vi[i], h = g_hi[i];
    int pe = g_off_e[h] + atomicAdd(&g_cur_e[h], 1);
    g_nbr_e[pe] = v;
}

__global__ void k_fill_v() {
    int i = blockIdx.x * blockDim.x + threadIdx.x;
    if (i >= NNZ) return;
    int v = g_vi[i], h = g_hi[i];
    int pv = g_off_v[v] + atomicAdd(&g_cur_v[v], 1);
    g_nbr_v[pv] = h;
}

// ---------------- packing kernels ----------------
__global__ void k_packW(const float* __restrict__ W1, const float* __restrict__ W2,
                        const float* __restrict__ W3) {
    int i = blockIdx.x * blockDim.x + threadIdx.x;
    if (i >= WP_TOTAL) return;
    const float* W; int base, N;
    if (i < WP2_OFF)      { W = W1; base = i;           N = HID;  }
    else if (i < WP3_OFF) { W = W2; base = i - WP2_OFF; N = HID;  }
    else                  { W = W3; base = i - WP3_OFF; N = F_OUT; }
    int k2 = base / N, n = base % N;
    __half2 h = __floats2half2_rn(W[(2 * k2) * N + n], W[(2 * k2 + 1) * N + n]);
    g_Wp[i] = *(uint32_t*)&h;
}

__global__ void k_packX(const float* __restrict__ x, __half* __restrict__ xh) {
    int i = blockIdx.x * blockDim.x + threadIdx.x;
    if (i >= N_NODES * F_IN / 8) return;
    const float4* p = (const float4*)(x + (size_t)i * 8);
    float4 a = p[0], b = p[1];
    uint4 o;
    __half2 h;
    h = __floats2half2_rn(a.x, a.y); o.x = *(uint32_t*)&h;
    h = __floats2half2_rn(a.z, a.w); o.y = *(uint32_t*)&h;
    h = __floats2half2_rn(b.x, b.y); o.z = *(uint32_t*)&h;
    h = __floats2half2_rn(b.z, b.w); o.w = *(uint32_t*)&h;
    ((uint4*)xh)[i] = o;
}

// ---------------- FP16 tensor-core GEMM (fp32 accum), fp16 out --------------
__global__ __launch_bounds__(256, 2)
void k_hgemm(const __half* __restrict__ A, const uint32_t* __restrict__ Bp,
             __half* __restrict__ C, int M, int K, int N) {
    __shared__ uint32_t As2[2][8][132];
    __shared__ uint32_t Bs2[2][8][132];
    const int t = threadIdx.x;
    const int lane = t & 31;
    const int warp = t >> 5;
    const int warp_m = (warp & 1) * 64;
    const int warp_n = (warp >> 1) * 32;
    const int gid = lane >> 2;
    const int tg  = lane & 3;

    const int arow = t >> 1, ak2 = (t & 1) * 4;
    const int bk2 = t >> 5,  bn4 = (t & 31) * 4;

    const int bm = blockIdx.y * 128, bn = blockIdx.x * 128;
    const bool arow_ok = (bm + arow) < M;
    const __half* Ap = A + (size_t)(bm + arow) * K + ak2 * 2;
    const uint32_t* Bpp = Bp + (size_t)bk2 * N + bn + bn4;

    float acc[4][4][4] = {};
    uint4 ah, bw;

    ah = arow_ok ? *(const uint4*)Ap : make_uint4(0, 0, 0, 0);
    bw = *(const uint4*)Bpp;
    As2[0][ak2 + 0][arow] = ah.x;
    As2[0][ak2 + 1][arow] = ah.y;
    As2[0][ak2 + 2][arow] = ah.z;
    As2[0][ak2 + 3][arow] = ah.w;
    Bs2[0][bk2][bn4 + 0] = bw.x;
    Bs2[0][bk2][bn4 + 1] = bw.y;
    Bs2[0][bk2][bn4 + 2] = bw.z;
    Bs2[0][bk2][bn4 + 3] = bw.w;
    __syncthreads();

    const int nk = K >> 4;
    for (int kt = 0; kt < nk; kt++) {
        const int cur = kt & 1, nxt = cur ^ 1;
        if (kt + 1 < nk) {
            ah = arow_ok ? *(const uint4*)(Ap + (kt + 1) * 16) : make_uint4(0, 0, 0, 0);
            bw = *(const uint4*)(Bpp + (size_t)(kt + 1) * 8 * N);
        }

        uint32_t af[4][4], bf[4][2];
        #pragma unroll
        for (int mt = 0; mt < 4; mt++) {
            int r = warp_m + mt * 16 + gid;
            af[mt][0] = As2[cur][tg][r];
            af[mt][1] = As2[cur][tg][r + 8];
            af[mt][2] = As2[cur][tg + 4][r];
            af[mt][3] = As2[cur][tg + 4][r + 8];
        }
        #pragma unroll
        for (int nt = 0; nt < 4; nt++) {
            int c = warp_n + nt * 8 + gid;
            bf[nt][0] = Bs2[cur][tg][c];
            bf[nt][1] = Bs2[cur][tg + 4][c];
        }
        #pragma unroll
        for (int mt = 0; mt < 4; mt++)
            #pragma unroll
            for (int nt = 0; nt < 4; nt++) {
                asm volatile(
                    "mma.sync.aligned.m16n8k16.row.col.f32.f16.f16.f32 "
                    "{%0,%1,%2,%3}, {%4,%5,%6,%7}, {%8,%9}, {%0,%1,%2,%3};"
                    : "+f"(acc[mt][nt][0]), "+f"(acc[mt][nt][1]),
                      "+f"(acc[mt][nt][2]), "+f"(acc[mt][nt][3])
                    : "r"(af[mt][0]), "r"(af[mt][1]), "r"(af[mt][2]), "r"(af[mt][3]),
                      "r"(bf[nt][0]), "r"(bf[nt][1]));
            }

        if (kt + 1 < nk) {
            As2[nxt][ak2 + 0][arow] = ah.x;
            As2[nxt][ak2 + 1][arow] = ah.y;
            As2[nxt][ak2 + 2][arow] = ah.z;
            As2[nxt][ak2 + 3][arow] = ah.w;
            Bs2[nxt][bk2][bn4 + 0] = bw.x;
            Bs2[nxt][bk2][bn4 + 1] = bw.y;
            Bs2[nxt][bk2][bn4 + 2] = bw.z;
            Bs2[nxt][bk2][bn4 + 3] = bw.w;
        }
        __syncthreads();
    }

    #pragma unroll
    for (int mt = 0; mt < 4; mt++) {
        int r0 = bm + warp_m + mt * 16 + gid;
        #pragma unroll
        for (int nt = 0; nt < 4; nt++) {
            int c0 = bn + warp_n + nt * 8 + tg * 2;
            if (r0 < M)
                *(__half2*)&C[(size_t)r0 * N + c0] =
                    __floats2half2_rn(acc[mt][nt][0], acc[mt][nt][1]);
            if (r0 + 8 < M)
                *(__half2*)&C[(size_t)(r0 + 8) * N + c0] =
                    __floats2half2_rn(acc[mt][nt][2], acc[mt][nt][3]);
        }
    }
}

// ---------------- CSR gathers over fp16 rows ----------------
// OUT_MODE: 0 = fp16, no bias (v->e). 1 = fp16 + bias + ELU. 2 = fp32 + bias.
template<int LPG, int RPB, int OUT_MODE>
__global__ __launch_bounds__(LPG * RPB)
void k_gather(const uint4* __restrict__ src,
              const int* __restrict__ off,
              const int* __restrict__ nbr,
              const float* __restrict__ dscale,
              const float* __restrict__ bias,
              void* __restrict__ dst, int nrows) {
    const int group = threadIdx.x / LPG;
    const int lane  = threadIdx.x % LPG;
    const int row = blockIdx.x * RPB + group;
    if (row >= nrows) return;
    const int s0 = off[row], s1 = off[row + 1];

    float2 acc[4] = {};
    int j = s0;
    for (; j + 1 < s1; j += 2) {
        int n0 = __ldg(&nbr[j]);
        int n1 = __ldg(&nbr[j + 1]);
        uint4 p0 = src[(size_t)n0 * LPG + lane];
        uint4 p1 = src[(size_t)n1 * LPG + lane];
        const __half2* h0 = (const __half2*)&p0;
        const __half2* h1 = (const __half2*)&p1;
        #pragma unroll
        for (int i = 0; i < 4; i++) {
            float2 f = __half22float2(__hadd2(h0[i], h1[i]));
            acc[i].x += f.x;
            acc[i].y += f.y;
        }
    }
    if (j < s1) {
        int n0 = __ldg(&nbr[j]);
        uint4 p0 = src[(size_t)n0 * LPG + lane];
        const __half2* h0 = (const __half2*)&p0;
        #pragma unroll
        for (int i = 0; i < 4; i++) {
            float2 a = __half22float2(h0[i]);
            acc[i].x += a.x;
            acc[i].y += a.y;
        }
    }
    float s = dscale[row];
    float v[8];
    #pragma unroll
    for (int i = 0; i < 4; i++) {
        v[2*i]   = acc[i].x * s;
        v[2*i+1] = acc[i].y * s;
    }
    if (OUT_MODE == 0) {
        uint4 outw;
        __half2* oh = (__half2*)&outw;
        #pragma unroll
        for (int i = 0; i < 4; i++)
            oh[i] = __floats2half2_rn(v[2*i], v[2*i+1]);
        ((uint4*)dst)[(size_t)row * LPG + lane] = outw;
    } else {
        const float* bp = bias + lane * 8;
        #pragma unroll
        for (int i = 0; i < 8; i++) v[i] += bp[i];
        if (OUT_MODE == 1) {
            #pragma unroll
            for (int i = 0; i < 8; i++) v[i] = v[i] > 0.f ? v[i] : expm1f(v[i]);
            uint4 outw;
            __half2* oh = (__half2*)&outw;
            #pragma unroll
            for (int i = 0; i < 4; i++)
                oh[i] = __floats2half2_rn(v[2*i], v[2*i+1]);
            ((uint4*)dst)[(size_t)row * LPG + lane] = outw;
        } else {
            float4* dp = (float4*)dst + (size_t)row * (LPG * 2) + lane * 2;
            dp[0] = make_float4(v[0], v[1], v[2], v[3]);
            dp[1] = make_float4(v[4], v[5], v[6], v[7]);
        }
    }
}

// ---------------- host driver ----------------
static inline int cdiv(int a, int b) { return (a + b - 1) / b; }

extern "C" void kernel_launch(void* const* d_in, const int* in_sizes, int n_in,
                              void* d_out, int out_size) {
    const float* x  = (const float*)d_in[0];
    const void*  ei = d_in[1];
    const float* W1 = (const float*)d_in[3];
    const float* b1 = (const float*)d_in[4];
    const float* W2 = (const float*)d_in[5];
    const float* b2 = (const float*)d_in[6];
    const float* W3 = (const float*)d_in[7];
    const float* b3 = (const float*)d_in[8];

    float *A, *B, *C, *inv_v, *inv_e;
    uint32_t* Wp;
    int *off_v, *off_e, *nbr_v, *nbr_e;
    cudaGetSymbolAddress((void**)&A, g_bufA);
    cudaGetSymbolAddress((void**)&B, g_bufB);
    cudaGetSymbolAddress((void**)&C, g_bufC);
    cudaGetSymbolAddress((void**)&Wp, g_Wp);
    cudaGetSymbolAddress((void**)&inv_v, g_inv_v);
    cudaGetSymbolAddress((void**)&inv_e, g_inv_e);
    cudaGetSymbolAddress((void**)&off_v, g_off_v);
    cudaGetSymbolAddress((void**)&off_e, g_off_e);
    cudaGetSymbolAddress((void**)&nbr_v, g_nbr_v);
    cudaGetSymbolAddress((void**)&nbr_e, g_nbr_e);

    const int TB = 256;

    __half* msg = (__half*)A;
    __half* xh  = (__half*)B;   // layer-1 A operand, later reused as xe
    __half* xe  = (__half*)B;
    __half* h   = (__half*)C;
    float*  out = (float*)d_out;

    // ONE extra stream (R12-proven resource budget). s2 carries pack + GEMM1,
    // then the v-side CSR chain (hidden under fill_e + gather-e1 on stream 0).
    cudaStream_t s2;
    cudaStreamCreateWithFlags(&s2, cudaStreamNonBlocking);
    cudaEvent_t evFork, evConv, evG1, evV;
    cudaEventCreateWithFlags(&evFork, cudaEventDisableTiming);
    cudaEventCreateWithFlags(&evConv, cudaEventDisableTiming);
    cudaEventCreateWithFlags(&evG1,   cudaEventDisableTiming);
    cudaEventCreateWithFlags(&evV,    cudaEventDisableTiming);

    cudaEventRecord(evFork, 0);
    cudaStreamWaitEvent(s2, evFork, 0);

    // ---- s2: weight/x packing + layer-1 GEMM ----
    k_packW<<<cdiv(WP_TOTAL, TB), TB, 0, s2>>>(W1, W2, W3);
    k_packX<<<cdiv(N_NODES * F_IN / 8, TB), TB, 0, s2>>>(x, xh);
    {
        dim3 gg(HID / 128, cdiv(N_NODES, 128));
        k_hgemm<<<gg, 256, 0, s2>>>(xh, Wp + WP1_OFF, msg, N_NODES, F_IN, HID);
    }
    cudaEventRecord(evG1, s2);

    // ---- stream 0: shared prep ----
    k_zero_all<<<cdiv(N_NODES, TB), TB>>>((const int*)ei);
    k_convert<<<cdiv(NNZ, TB), TB>>>(ei);
    cudaEventRecord(evConv, 0);

    // ---- s2 (continued): v-side CSR chain (needed only by gather-v1) ----
    cudaStreamWaitEvent(s2, evConv, 0);
    k_scanA<<<NCHUNK, 256, 0, s2>>>(1);
    k_scanC<<<NCHUNK, 256, 0, s2>>>(1);
    k_fill_v<<<cdiv(NNZ, TB), TB, 0, s2>>>();
    cudaEventRecord(evV, s2);

    // ---- stream 0: e-side chain ----
    k_scanA<<<NCHUNK, 256>>>(0);
    k_scanC<<<NCHUNK, 256>>>(0);
    k_fill_e<<<cdiv(NNZ, TB), TB>>>();

    cudaStreamWaitEvent(0, evG1, 0);

    // ---- layer 1 gathers ----
    k_gather<32, 8, 0><<<cdiv(N_HEDGES, 8), 256>>>(
        (const uint4*)msg, off_e, nbr_e, inv_e, nullptr, xe, N_HEDGES);
    cudaStreamWaitEvent(0, evV, 0);
    k_gather<32, 8, 1><<<cdiv(N_NODES, 8), 256>>>(
        (const uint4*)xe, off_v, nbr_v, inv_v, b1, h, N_NODES);

    // ---- layer 2 ----
    {
        dim3 gg(HID / 128, cdiv(N_NODES, 128));
        k_hgemm<<<gg, 256>>>(h, Wp + WP2_OFF, msg, N_NODES, HID, HID);
        k_gather<32, 8, 0><<<cdiv(N_HEDGES, 8), 256>>>(
            (const uint4*)msg, off_e, nbr_e, inv_e, nullptr, xe, N_HEDGES);
        k_gather<32, 8, 1><<<cdiv(N_NODES, 8), 256>>>(
            (const uint4*)xe, off_v, nbr_v, inv_v, b2, h, N_NODES);
    }
    // ---- layer 3 ----
    {
        dim3 gg(F_OUT / 128, cdiv(N_NODES, 128));
        k_hgemm<<<gg, 256>>>(h, Wp + WP3_OFF, msg, N_NODES, HID, F_OUT);
        k_gather<16, 16, 0><<<cdiv(N_HEDGES, 16), 256>>>(
            (const uint4*)msg, off_e, nbr_e, inv_e, nullptr, xe, N_HEDGES);
        k_gather<16, 16, 2><<<cdiv(N_NODES, 16), 256>>>(
            (const uint4*)xe, off_v, nbr_v, inv_v, b3, out, N_NODES);
    }
}